// round 11
// baseline (speedup 1.0000x reference)
#include <cuda_runtime.h>
#include <cuda_fp16.h>
#include <math.h>
#include <string.h>

#define NSEQ 256
#define DIM 64
#define NH 4
#define NPOS (NSEQ * NSEQ)
#define NEGINF -1000000000.0f

typedef unsigned long long u64;
typedef unsigned int u32;

// ---- packed fp32x2 helpers (proj + epilogue) ----
__device__ __forceinline__ u64 pack2(float lo, float hi) {
    u64 r; asm("mov.b64 %0, {%1, %2};" : "=l"(r) : "f"(lo), "f"(hi)); return r;
}
__device__ __forceinline__ u64 dup2(float v) { return pack2(v, v); }
__device__ __forceinline__ void unpack2(u64 v, float& lo, float& hi) {
    asm("mov.b64 {%0, %1}, %2;" : "=f"(lo), "=f"(hi) : "l"(v));
}
__device__ __forceinline__ void fma2(u64& d, u64 a, u64 b) {
    asm("fma.rn.f32x2 %0, %1, %2, %0;" : "+l"(d) : "l"(a), "l"(b));
}
__device__ __forceinline__ u64 mul2(u64 a, u64 b) {
    u64 r; asm("mul.rn.f32x2 %0, %1, %2;" : "=l"(r) : "l"(a), "l"(b)); return r;
}

// pack two floats as fp16x2 (low half = a)
__device__ __forceinline__ u32 hpack(float a, float b) {
    __half2 p = __floats2half2_rn(a, b);
    u32 r; memcpy(&r, &p, 4); return r;
}

// mma.sync m16n8k16 row.col f32.f16.f16.f32, D = A*B + D
__device__ __forceinline__ void mma16816(float* c, const u32* a, const u32* b) {
    asm volatile(
        "mma.sync.aligned.m16n8k16.row.col.f32.f16.f16.f32 "
        "{%0,%1,%2,%3}, {%4,%5,%6,%7}, {%8,%9}, {%0,%1,%2,%3};"
        : "+f"(c[0]), "+f"(c[1]), "+f"(c[2]), "+f"(c[3])
        : "r"(a[0]), "r"(a[1]), "r"(a[2]), "r"(a[3]), "r"(b[0]), "r"(b[1]));
}

// Scratch
__device__ float g_q[NPOS * DIM];
__device__ float g_k[NPOS * DIM];
__device__ float g_v[NPOS * DIM];
__device__ float g_gate[NPOS * DIM];
__device__ float g_bm[NH * NSEQ * NSEQ];   // [h][q][k]

// ---------------------------------------------------------------------------
// Kernel 1 (persistent): LayerNorm + Q/K/V/Gate projections + fused bias/mask.
// ---------------------------------------------------------------------------
__global__ __launch_bounds__(256, 2) void proj_kernel(
    const float* __restrict__ x, const int* __restrict__ mask,
    const float* __restrict__ ln_s, const float* __restrict__ ln_b,
    const float* __restrict__ Wq, const float* __restrict__ Wk,
    const float* __restrict__ Wv, const float* __restrict__ Wg,
    const float* __restrict__ bg, const float* __restrict__ Wb)
{
    extern __shared__ float sm[];
    float* s_wq = sm;                 // 4096
    float* s_wk = s_wq + 4096;
    float* s_wv = s_wk + 4096;
    float* s_wg = s_wv + 4096;
    float* s_wb = s_wg + 4096;        // 256
    float* s_xt = s_wb + 256;         // [d][pos] stride 66
    float* s_bg = s_xt + 64 * 66;
    float* s_ls = s_bg + 64;
    float* s_lb = s_ls + 64;

    const int tid = threadIdx.x;
    for (int idx = tid; idx < 4096; idx += 256) {
        s_wq[idx] = Wq[idx];
        s_wk[idx] = Wk[idx];
        s_wv[idx] = Wv[idx];
        s_wg[idx] = Wg[idx];
    }
    s_wb[tid] = Wb[tid];
    if (tid < 64) { s_bg[tid] = bg[tid]; s_ls[tid] = ln_s[tid]; s_lb[tid] = ln_b[tid]; }
    __syncthreads();

    const int lane = tid & 31;
    const int wrp  = tid >> 5;
    const int jj   = tid & 63;
    const int pz   = tid >> 6;
    const int ph   = tid >> 2;
    const int hh   = tid & 3;

    for (int c = blockIdx.x; c < 1024; c += gridDim.x) {
        const int p0 = c * 64;

        for (int pp = wrp; pp < 64; pp += 8) {
            const float* xr = x + (p0 + pp) * DIM;
            float a = xr[lane];
            float b = xr[lane + 32];
            float sum = a + b;
            float sq = a * a + b * b;
            #pragma unroll
            for (int off = 16; off > 0; off >>= 1) {
                sum += __shfl_xor_sync(0xffffffffu, sum, off);
                sq  += __shfl_xor_sync(0xffffffffu, sq, off);
            }
            float mu  = sum * (1.0f / 64.0f);
            float var = sq * (1.0f / 64.0f) - mu * mu;
            float inv = rsqrtf(var + 1e-5f);
            s_xt[lane * 66 + pp]        = (a - mu) * inv * s_ls[lane]      + s_lb[lane];
            s_xt[(lane + 32) * 66 + pp] = (b - mu) * inv * s_ls[lane + 32] + s_lb[lane + 32];
        }
        __syncthreads();

        // bias + mask -> g_bm[h][q][k]
        {
            float acc = 0.0f;
            #pragma unroll 8
            for (int d = 0; d < 64; ++d)
                acc = fmaf(s_xt[d * 66 + ph], s_wb[d * 4 + hh], acc);
            const int flat = p0 + ph;
            const int r = flat >> 8;    // q
            const int cc = flat & 255;  // k
            g_bm[hh * 65536 + r * 256 + cc] = (mask[flat] != 0) ? acc : NEGINF;
        }

        u64 aq[8], ak[8], av[8], ag[8];
        #pragma unroll
        for (int m = 0; m < 8; ++m) { aq[m] = 0ull; ak[m] = 0ull; av[m] = 0ull; ag[m] = 0ull; }

        #pragma unroll 2
        for (int d = 0; d < 64; ++d) {
            const u64 wq2 = dup2(s_wq[d * 64 + jj]);
            const u64 wk2 = dup2(s_wk[d * 64 + jj]);
            const u64 wv2 = dup2(s_wv[d * 64 + jj]);
            const u64 wg2 = dup2(s_wg[d * 64 + jj]);
            const u64* xp = (const u64*)(s_xt + d * 66 + pz * 16);
            #pragma unroll
            for (int m = 0; m < 8; ++m) {
                const u64 xv = xp[m];
                fma2(aq[m], xv, wq2);
                fma2(ak[m], xv, wk2);
                fma2(av[m], xv, wv2);
                fma2(ag[m], xv, wg2);
            }
        }

        #pragma unroll
        for (int m = 0; m < 8; ++m) {
            const int o = (p0 + pz * 16 + 2 * m) * 64 + jj;
            float v0, v1;
            unpack2(aq[m], v0, v1); g_q[o] = v0; g_q[o + 64] = v1;
            unpack2(ak[m], v0, v1); g_k[o] = v0; g_k[o + 64] = v1;
            unpack2(av[m], v0, v1); g_v[o] = v0; g_v[o + 64] = v1;
            unpack2(ag[m], v0, v1);
            g_gate[o]      = 1.0f / (1.0f + __expf(-(v0 + s_bg[jj])));
            g_gate[o + 64] = 1.0f / (1.0f + __expf(-(v1 + s_bg[jj])));
        }
        __syncthreads();
    }
}

// ---------------------------------------------------------------------------
// Attention unit: warp computes O[64 q][16 d], row-sums, for (i, h, q0).
// ---------------------------------------------------------------------------
__device__ __forceinline__ void run_unit(
    int i, int h, int q0, int g, int t,
    const u32* __restrict__ s_kw, const u32* __restrict__ s_vw,
    float oc[4][2][4], float ls[4][2])
{
    // Q frags (pre-scaled by 1/sqrt(16))
    u32 qa[4][4];
    {
        const float2* qp = (const float2*)g_q;
        #pragma unroll
        for (int mt = 0; mt < 4; ++mt) {
            const int r0 = i * 256 + q0 + mt * 16 + g;
            float2 f0 = qp[r0 * 32 + h * 8 + t];
            float2 f1 = qp[(r0 + 8) * 32 + h * 8 + t];
            float2 f2 = qp[r0 * 32 + h * 8 + 4 + t];
            float2 f3 = qp[(r0 + 8) * 32 + h * 8 + 4 + t];
            qa[mt][0] = hpack(f0.x * 0.25f, f0.y * 0.25f);
            qa[mt][1] = hpack(f1.x * 0.25f, f1.y * 0.25f);
            qa[mt][2] = hpack(f2.x * 0.25f, f2.y * 0.25f);
            qa[mt][3] = hpack(f3.x * 0.25f, f3.y * 0.25f);
        }
    }
    #pragma unroll
    for (int mt = 0; mt < 4; ++mt) {
        ls[mt][0] = 0.f; ls[mt][1] = 0.f;
        #pragma unroll
        for (int nd = 0; nd < 2; ++nd)
            #pragma unroll
            for (int r = 0; r < 4; ++r) oc[mt][nd][r] = 0.f;
    }

    const float2* bp = (const float2*)g_bm + h * 32768 + (q0 + g) * 128 + t;
    const u32* kp = s_kw + h * 2048 + g * 8 + t;
    const u32* vp = s_vw + (h * 16 + g) * 132 + t;

    float2 bA[16], bB[16];   // [mt][nt][rr] -> mt*4 + nt*2 + rr
    #pragma unroll
    for (int mt = 0; mt < 4; ++mt)
        #pragma unroll
        for (int nt = 0; nt < 2; ++nt)
            #pragma unroll
            for (int rr = 0; rr < 2; ++rr)
                bA[mt * 4 + nt * 2 + rr] = __ldg(bp + mt * 2048 + rr * 1024 + nt * 4);

    auto body = [&](int c, const float2* bu, float2* bpf, int cn) {
        // K frags
        u32 kb[2][2];
        #pragma unroll
        for (int nt = 0; nt < 2; ++nt) {
            kb[nt][0] = kp[(c * 16 + nt * 8) * 8];
            kb[nt][1] = kp[(c * 16 + nt * 8) * 8 + 4];
        }
        // S frags init = bias, then QK MMA
        float sc[4][2][4];
        #pragma unroll
        for (int mt = 0; mt < 4; ++mt)
            #pragma unroll
            for (int nt = 0; nt < 2; ++nt) {
                sc[mt][nt][0] = bu[mt * 4 + nt * 2 + 0].x;
                sc[mt][nt][1] = bu[mt * 4 + nt * 2 + 0].y;
                sc[mt][nt][2] = bu[mt * 4 + nt * 2 + 1].x;
                sc[mt][nt][3] = bu[mt * 4 + nt * 2 + 1].y;
            }
        #pragma unroll
        for (int mt = 0; mt < 4; ++mt)
            #pragma unroll
            for (int nt = 0; nt < 2; ++nt)
                mma16816(sc[mt][nt], qa[mt], kb[nt]);
        // prefetch bias for chunk cn
        if (cn < 16) {
            #pragma unroll
            for (int mt = 0; mt < 4; ++mt)
                #pragma unroll
                for (int nt = 0; nt < 2; ++nt)
                    #pragma unroll
                    for (int rr = 0; rr < 2; ++rr)
                        bpf[mt * 4 + nt * 2 + rr] =
                            __ldg(bp + mt * 2048 + rr * 1024 + cn * 8 + nt * 4);
        }
        // exp + row sums + P frags
        u32 pa[4][4];
        #pragma unroll
        for (int mt = 0; mt < 4; ++mt) {
            float e00 = __expf(sc[mt][0][0]);
            float e01 = __expf(sc[mt][0][1]);
            float e02 = __expf(sc[mt][0][2]);
            float e03 = __expf(sc[mt][0][3]);
            float e10 = __expf(sc[mt][1][0]);
            float e11 = __expf(sc[mt][1][1]);
            float e12 = __expf(sc[mt][1][2]);
            float e13 = __expf(sc[mt][1][3]);
            ls[mt][0] += (e00 + e01) + (e10 + e11);
            ls[mt][1] += (e02 + e03) + (e12 + e13);
            pa[mt][0] = hpack(e00, e01);
            pa[mt][1] = hpack(e02, e03);
            pa[mt][2] = hpack(e10, e11);
            pa[mt][3] = hpack(e12, e13);
        }
        // V frags (hi part 0, lo part 1)
        u32 vb[2][2][2];
        #pragma unroll
        for (int part = 0; part < 2; ++part)
            #pragma unroll
            for (int nd = 0; nd < 2; ++nd) {
                const u32* vq = vp + (part * 64 + nd * 8) * 132 + c * 8;
                vb[part][nd][0] = vq[0];
                vb[part][nd][1] = vq[4];
            }
        // PV MMAs
        #pragma unroll
        for (int mt = 0; mt < 4; ++mt)
            #pragma unroll
            for (int nd = 0; nd < 2; ++nd) {
                mma16816(oc[mt][nd], pa[mt], vb[0][nd]);
                mma16816(oc[mt][nd], pa[mt], vb[1][nd]);
            }
    };

    #pragma unroll 1
    for (int cc = 0; cc < 8; ++cc) {
        body(2 * cc,     bA, bB, 2 * cc + 1);
        body(2 * cc + 1, bB, bA, 2 * cc + 2);
    }
}

// ---------------------------------------------------------------------------
// Kernel 2: MMA attention + gate + output projection, fused. Block = row i.
// 256 threads = 8 warps; warp = (h = w&3, q-quarter pair). Two 64-q units.
// ---------------------------------------------------------------------------
__global__ __launch_bounds__(256, 1) void attn_kernel(
    const float* __restrict__ Wo, const float* __restrict__ bo,
    float* __restrict__ out)
{
    extern __shared__ float smf[];
    u32* s_kw = (u32*)smf;                              // 8192 u32 = 32 KB
    __half* s_vt = (__half*)(smf + 8192);               // 128 rows x 264 fp16
    const u32* s_vw = (const u32*)(smf + 8192);
    // epilogue aliases (after sync):
    float* s_goT = smf;             // [64][260]
    float* s_wo  = smf + 16640;     // 4096
    float* s_bo  = smf + 20736;     // 64

    const int i = blockIdx.x;
    const int tid = threadIdx.x;
    const int w = tid >> 5, lane = tid & 31;
    const int h = w & 3, qhi = w >> 2;
    const int g = lane >> 2, t = lane & 3;

    // ---- stage K (fp16 pairs) and V^T (fp16 hi/lo, transposed) ----
    {
        const float4* gk4 = (const float4*)(g_k + i * 16384);
        const float4* gv4 = (const float4*)(g_v + i * 16384);
        #pragma unroll
        for (int it = 0; it < 16; ++it) {
            const int idx = it * 256 + tid;
            const int key = idx >> 4, f4 = idx & 15;
            const int hh = f4 >> 2, quad = f4 & 3;
            float4 kv = gk4[idx];
            const int ka = (hh * 256 + key) * 8 + quad * 2;
            s_kw[ka]     = hpack(kv.x, kv.y);
            s_kw[ka + 1] = hpack(kv.z, kv.w);
            float4 vv = gv4[idx];
            float ve[4] = {vv.x, vv.y, vv.z, vv.w};
            #pragma unroll
            for (int e = 0; e < 4; ++e) {
                __half hi = __float2half_rn(ve[e]);
                __half lo = __float2half_rn(ve[e] - __half2float(hi));
                const int dl = hh * 16 + quad * 4 + e;
                s_vt[dl * 264 + key]          = hi;
                s_vt[(64 + dl) * 264 + key]   = lo;
            }
        }
    }
    __syncthreads();

    float oc[2][4][2][4];
    float inv[2][4][2];
    #pragma unroll 1
    for (int u = 0; u < 2; ++u) {
        const int q0 = qhi * 128 + u * 64;
        float ls[4][2];
        run_unit(i, h, q0, g, t, s_kw, s_vw, oc[u], ls);
        #pragma unroll
        for (int mt = 0; mt < 4; ++mt)
            #pragma unroll
            for (int rr = 0; rr < 2; ++rr) {
                float v = ls[mt][rr];
                v += __shfl_xor_sync(0xffffffffu, v, 1);
                v += __shfl_xor_sync(0xffffffffu, v, 2);
                inv[u][mt][rr] = 1.0f / v;
            }
    }

    // normalize + gate (registers only)
    {
        const float2* gp = (const float2*)g_gate;
        #pragma unroll
        for (int u = 0; u < 2; ++u) {
            const int q0 = qhi * 128 + u * 64;
            #pragma unroll
            for (int mt = 0; mt < 4; ++mt) {
                const int qr = i * 256 + q0 + mt * 16 + g;
                #pragma unroll
                for (int nd = 0; nd < 2; ++nd) {
                    float2 g0 = gp[qr * 32 + h * 8 + nd * 4 + t];
                    float2 g1 = gp[(qr + 8) * 32 + h * 8 + nd * 4 + t];
                    oc[u][mt][nd][0] *= inv[u][mt][0] * g0.x;
                    oc[u][mt][nd][1] *= inv[u][mt][0] * g0.y;
                    oc[u][mt][nd][2] *= inv[u][mt][1] * g1.x;
                    oc[u][mt][nd][3] *= inv[u][mt][1] * g1.y;
                }
            }
        }
    }

    __syncthreads();   // all K/V smem reads done; re-use as goT

    // write goT [d][q] stride 260
    #pragma unroll
    for (int u = 0; u < 2; ++u) {
        const int q0 = qhi * 128 + u * 64;
        #pragma unroll
        for (int mt = 0; mt < 4; ++mt) {
            const int qr = q0 + mt * 16 + g;
            #pragma unroll
            for (int nd = 0; nd < 2; ++nd) {
                const int d0 = h * 16 + nd * 8 + 2 * t;
                s_goT[d0 * 260 + qr]           = oc[u][mt][nd][0];
                s_goT[(d0 + 1) * 260 + qr]     = oc[u][mt][nd][1];
                s_goT[d0 * 260 + qr + 8]       = oc[u][mt][nd][2];
                s_goT[(d0 + 1) * 260 + qr + 8] = oc[u][mt][nd][3];
            }
        }
    }
    for (int idx = tid; idx < 4096; idx += 256) s_wo[idx] = Wo[idx];
    if (tid < 64) s_bo[tid] = bo[tid];
    __syncthreads();

    // out = go @ Wo + bo
    const int jj = tid & 63;
    const int pz = tid >> 6;    // 0..3
    u64 oa[32];
    #pragma unroll
    for (int m = 0; m < 32; ++m) oa[m] = 0ull;
    #pragma unroll 2
    for (int d = 0; d < 64; ++d) {
        const u64 w2 = dup2(s_wo[d * 64 + jj]);
        const u64* gpt = (const u64*)(s_goT + d * 260 + pz * 64);
        #pragma unroll
        for (int m = 0; m < 32; ++m) fma2(oa[m], gpt[m], w2);
    }
    const float bov = s_bo[jj];
    float* op = out + (i * 256 + pz * 64) * 64 + jj;
    #pragma unroll
    for (int m = 0; m < 32; ++m) {
        float lo, hi;
        unpack2(oa[m], lo, hi);
        op[(2 * m) * 64]     = lo + bov;
        op[(2 * m + 1) * 64] = hi + bov;
    }
}

// ---------------------------------------------------------------------------
extern "C" void kernel_launch(void* const* d_in, const int* in_sizes, int n_in,
                              void* d_out, int out_size)
{
    const float* x    = (const float*)d_in[0];
    const int*   mask = (const int*)d_in[1];
    const float* ln_s = (const float*)d_in[2];
    const float* ln_b = (const float*)d_in[3];
    const float* Wq   = (const float*)d_in[4];
    const float* Wk   = (const float*)d_in[5];
    const float* Wv   = (const float*)d_in[6];
    const float* Wg   = (const float*)d_in[7];
    const float* bg   = (const float*)d_in[8];
    const float* Wb   = (const float*)d_in[9];
    const float* Wo   = (const float*)d_in[10];
    const float* bo   = (const float*)d_in[11];
    float* out = (float*)d_out;
    (void)in_sizes; (void)n_in; (void)out_size;

    const int sm1 = (4 * 4096 + 256 + 64 * 66 + 3 * 64) * (int)sizeof(float);
    const int sm2 = 100352;   // 32 KB K + 66 KB V^T (epilogue aliases within)
    cudaFuncSetAttribute(proj_kernel, cudaFuncAttributeMaxDynamicSharedMemorySize, sm1);
    cudaFuncSetAttribute(attn_kernel, cudaFuncAttributeMaxDynamicSharedMemorySize, sm2);

    proj_kernel<<<296, 256, sm1>>>(x, mask, ln_s, ln_b, Wq, Wk, Wv, Wg, bg, Wb);
    attn_kernel<<<256, 256, sm2>>>(Wo, bo, out);
}

// round 14
// speedup vs baseline: 1.2130x; 1.2130x over previous
#include <cuda_runtime.h>
#include <cuda_fp16.h>
#include <math.h>
#include <string.h>

#define NSEQ 256
#define DIM 64
#define NH 4
#define NPOS (NSEQ * NSEQ)
#define NEGINF -1000000000.0f

typedef unsigned long long u64;
typedef unsigned int u32;

// ---- packed fp32x2 helpers (proj + epilogue) ----
__device__ __forceinline__ u64 pack2(float lo, float hi) {
    u64 r; asm("mov.b64 %0, {%1, %2};" : "=l"(r) : "f"(lo), "f"(hi)); return r;
}
__device__ __forceinline__ u64 dup2(float v) { return pack2(v, v); }
__device__ __forceinline__ void unpack2(u64 v, float& lo, float& hi) {
    asm("mov.b64 {%0, %1}, %2;" : "=f"(lo), "=f"(hi) : "l"(v));
}
__device__ __forceinline__ void fma2(u64& d, u64 a, u64 b) {
    asm("fma.rn.f32x2 %0, %1, %2, %0;" : "+l"(d) : "l"(a), "l"(b));
}
__device__ __forceinline__ u64 mul2(u64 a, u64 b) {
    u64 r; asm("mul.rn.f32x2 %0, %1, %2;" : "=l"(r) : "l"(a), "l"(b)); return r;
}

// pack two floats as fp16x2 (low half = a)
__device__ __forceinline__ u32 hpack(float a, float b) {
    __half2 p = __floats2half2_rn(a, b);
    u32 r; memcpy(&r, &p, 4); return r;
}

// mma.sync m16n8k16 row.col f32.f16.f16.f32, D = A*B + D
__device__ __forceinline__ void mma16816(float* c, const u32* a, const u32* b) {
    asm volatile(
        "mma.sync.aligned.m16n8k16.row.col.f32.f16.f16.f32 "
        "{%0,%1,%2,%3}, {%4,%5,%6,%7}, {%8,%9}, {%0,%1,%2,%3};"
        : "+f"(c[0]), "+f"(c[1]), "+f"(c[2]), "+f"(c[3])
        : "r"(a[0]), "r"(a[1]), "r"(a[2]), "r"(a[3]), "r"(b[0]), "r"(b[1]));
}

// Scratch
__device__ float g_q[NPOS * DIM];
__device__ float g_k[NPOS * DIM];
__device__ float g_v[NPOS * DIM];
__device__ float g_gate[NPOS * DIM];
__device__ float g_bm[NH * NSEQ * NSEQ];   // [h][q][k]

// ---------------------------------------------------------------------------
// Kernel 1 (persistent): LayerNorm + Q/K/V/Gate projections + fused bias/mask.
// ---------------------------------------------------------------------------
__global__ __launch_bounds__(256, 2) void proj_kernel(
    const float* __restrict__ x, const int* __restrict__ mask,
    const float* __restrict__ ln_s, const float* __restrict__ ln_b,
    const float* __restrict__ Wq, const float* __restrict__ Wk,
    const float* __restrict__ Wv, const float* __restrict__ Wg,
    const float* __restrict__ bg, const float* __restrict__ Wb)
{
    extern __shared__ float sm[];
    float* s_wq = sm;                 // 4096
    float* s_wk = s_wq + 4096;
    float* s_wv = s_wk + 4096;
    float* s_wg = s_wv + 4096;
    float* s_wb = s_wg + 4096;        // 256
    float* s_xt = s_wb + 256;         // [d][pos] stride 66
    float* s_bg = s_xt + 64 * 66;
    float* s_ls = s_bg + 64;
    float* s_lb = s_ls + 64;

    const int tid = threadIdx.x;
    for (int idx = tid; idx < 4096; idx += 256) {
        s_wq[idx] = Wq[idx];
        s_wk[idx] = Wk[idx];
        s_wv[idx] = Wv[idx];
        s_wg[idx] = Wg[idx];
    }
    s_wb[tid] = Wb[tid];
    if (tid < 64) { s_bg[tid] = bg[tid]; s_ls[tid] = ln_s[tid]; s_lb[tid] = ln_b[tid]; }
    __syncthreads();

    const int lane = tid & 31;
    const int wrp  = tid >> 5;
    const int jj   = tid & 63;
    const int pz   = tid >> 6;
    const int ph   = tid >> 2;
    const int hh   = tid & 3;

    for (int c = blockIdx.x; c < 1024; c += gridDim.x) {
        const int p0 = c * 64;

        for (int pp = wrp; pp < 64; pp += 8) {
            const float* xr = x + (p0 + pp) * DIM;
            float a = xr[lane];
            float b = xr[lane + 32];
            float sum = a + b;
            float sq = a * a + b * b;
            #pragma unroll
            for (int off = 16; off > 0; off >>= 1) {
                sum += __shfl_xor_sync(0xffffffffu, sum, off);
                sq  += __shfl_xor_sync(0xffffffffu, sq, off);
            }
            float mu  = sum * (1.0f / 64.0f);
            float var = sq * (1.0f / 64.0f) - mu * mu;
            float inv = rsqrtf(var + 1e-5f);
            s_xt[lane * 66 + pp]        = (a - mu) * inv * s_ls[lane]      + s_lb[lane];
            s_xt[(lane + 32) * 66 + pp] = (b - mu) * inv * s_ls[lane + 32] + s_lb[lane + 32];
        }
        __syncthreads();

        // bias + mask -> g_bm[h][q][k]
        {
            float acc = 0.0f;
            #pragma unroll 8
            for (int d = 0; d < 64; ++d)
                acc = fmaf(s_xt[d * 66 + ph], s_wb[d * 4 + hh], acc);
            const int flat = p0 + ph;
            const int r = flat >> 8;    // q
            const int cc = flat & 255;  // k
            g_bm[hh * 65536 + r * 256 + cc] = (mask[flat] != 0) ? acc : NEGINF;
        }

        u64 aq[8], ak[8], av[8], ag[8];
        #pragma unroll
        for (int m = 0; m < 8; ++m) { aq[m] = 0ull; ak[m] = 0ull; av[m] = 0ull; ag[m] = 0ull; }

        #pragma unroll 2
        for (int d = 0; d < 64; ++d) {
            const u64 wq2 = dup2(s_wq[d * 64 + jj]);
            const u64 wk2 = dup2(s_wk[d * 64 + jj]);
            const u64 wv2 = dup2(s_wv[d * 64 + jj]);
            const u64 wg2 = dup2(s_wg[d * 64 + jj]);
            const u64* xp = (const u64*)(s_xt + d * 66 + pz * 16);
            #pragma unroll
            for (int m = 0; m < 8; ++m) {
                const u64 xv = xp[m];
                fma2(aq[m], xv, wq2);
                fma2(ak[m], xv, wk2);
                fma2(av[m], xv, wv2);
                fma2(ag[m], xv, wg2);
            }
        }

        #pragma unroll
        for (int m = 0; m < 8; ++m) {
            const int o = (p0 + pz * 16 + 2 * m) * 64 + jj;
            float v0, v1;
            unpack2(aq[m], v0, v1); g_q[o] = v0; g_q[o + 64] = v1;
            unpack2(ak[m], v0, v1); g_k[o] = v0; g_k[o + 64] = v1;
            unpack2(av[m], v0, v1); g_v[o] = v0; g_v[o + 64] = v1;
            unpack2(ag[m], v0, v1);
            g_gate[o]      = 1.0f / (1.0f + __expf(-(v0 + s_bg[jj])));
            g_gate[o + 64] = 1.0f / (1.0f + __expf(-(v1 + s_bg[jj])));
        }
        __syncthreads();
    }
}

// ---------------------------------------------------------------------------
// Attention unit: warp computes O[32 q][16 d] + row sums for (i, h, q0).
// Bias double-buffer lives IN the S accumulators (scA/scB alternate).
// ---------------------------------------------------------------------------
__device__ __forceinline__ void run_unit(
    int i, int h, int q0, int g, int t,
    const u32* __restrict__ s_kw, const u32* __restrict__ s_vw,
    float oc[2][2][4], float ls[2][2])
{
    // Q frags (pre-scaled by 1/sqrt(16))
    u32 qa[2][4];
    {
        const float2* qp = (const float2*)g_q;
        #pragma unroll
        for (int mt = 0; mt < 2; ++mt) {
            const int r0 = i * 256 + q0 + mt * 16 + g;
            float2 f0 = qp[r0 * 32 + h * 8 + t];
            float2 f1 = qp[(r0 + 8) * 32 + h * 8 + t];
            float2 f2 = qp[r0 * 32 + h * 8 + 4 + t];
            float2 f3 = qp[(r0 + 8) * 32 + h * 8 + 4 + t];
            qa[mt][0] = hpack(f0.x * 0.25f, f0.y * 0.25f);
            qa[mt][1] = hpack(f1.x * 0.25f, f1.y * 0.25f);
            qa[mt][2] = hpack(f2.x * 0.25f, f2.y * 0.25f);
            qa[mt][3] = hpack(f3.x * 0.25f, f3.y * 0.25f);
        }
    }
    #pragma unroll
    for (int mt = 0; mt < 2; ++mt) {
        ls[mt][0] = 0.f; ls[mt][1] = 0.f;
        #pragma unroll
        for (int nd = 0; nd < 2; ++nd)
            #pragma unroll
            for (int r = 0; r < 4; ++r) oc[mt][nd][r] = 0.f;
    }

    const float2* bp = (const float2*)g_bm + h * 32768 + (q0 + g) * 128 + t;
    const u32* kp = s_kw + h * 2048 + g * 8 + t;
    const u32* vp = s_vw + (h * 16 + g) * 132 + t;

    float scA[2][2][4], scB[2][2][4];

    // prologue: bias chunk 0 -> scA
    #pragma unroll
    for (int mt = 0; mt < 2; ++mt)
        #pragma unroll
        for (int nt = 0; nt < 2; ++nt) {
            float2 b0 = __ldg(bp + mt * 2048 + nt * 4);
            float2 b1 = __ldg(bp + mt * 2048 + 1024 + nt * 4);
            scA[mt][nt][0] = b0.x; scA[mt][nt][1] = b0.y;
            scA[mt][nt][2] = b1.x; scA[mt][nt][3] = b1.y;
        }

    auto body = [&](int c, float sc[2][2][4], float scP[2][2][4]) {
        // K frags
        u32 kb[2][2];
        #pragma unroll
        for (int nt = 0; nt < 2; ++nt) {
            kb[nt][0] = kp[(c * 16 + nt * 8) * 8];
            kb[nt][1] = kp[(c * 16 + nt * 8) * 8 + 4];
        }
        // QK MMA into sc (already holds bias)
        #pragma unroll
        for (int mt = 0; mt < 2; ++mt)
            #pragma unroll
            for (int nt = 0; nt < 2; ++nt)
                mma16816(sc[mt][nt], qa[mt], kb[nt]);
        // prefetch bias for chunk c+1 straight into scP
        if (c < 15) {
            #pragma unroll
            for (int mt = 0; mt < 2; ++mt)
                #pragma unroll
                for (int nt = 0; nt < 2; ++nt) {
                    float2 b0 = __ldg(bp + mt * 2048 + (c + 1) * 8 + nt * 4);
                    float2 b1 = __ldg(bp + mt * 2048 + 1024 + (c + 1) * 8 + nt * 4);
                    scP[mt][nt][0] = b0.x; scP[mt][nt][1] = b0.y;
                    scP[mt][nt][2] = b1.x; scP[mt][nt][3] = b1.y;
                }
        }
        // exp + row sums + P frags
        u32 pa[2][4];
        #pragma unroll
        for (int mt = 0; mt < 2; ++mt) {
            float e00 = __expf(sc[mt][0][0]);
            float e01 = __expf(sc[mt][0][1]);
            float e02 = __expf(sc[mt][0][2]);
            float e03 = __expf(sc[mt][0][3]);
            float e10 = __expf(sc[mt][1][0]);
            float e11 = __expf(sc[mt][1][1]);
            float e12 = __expf(sc[mt][1][2]);
            float e13 = __expf(sc[mt][1][3]);
            ls[mt][0] += (e00 + e01) + (e10 + e11);
            ls[mt][1] += (e02 + e03) + (e12 + e13);
            pa[mt][0] = hpack(e00, e01);
            pa[mt][1] = hpack(e02, e03);
            pa[mt][2] = hpack(e10, e11);
            pa[mt][3] = hpack(e12, e13);
        }
        // V frags (single fp16)
        u32 vb[2][2];
        #pragma unroll
        for (int nd = 0; nd < 2; ++nd) {
            const u32* vq = vp + (nd * 8) * 132 + c * 8;
            vb[nd][0] = vq[0];
            vb[nd][1] = vq[4];
        }
        // PV MMAs
        #pragma unroll
        for (int mt = 0; mt < 2; ++mt)
            #pragma unroll
            for (int nd = 0; nd < 2; ++nd)
                mma16816(oc[mt][nd], pa[mt], vb[nd]);
    };

    #pragma unroll 1
    for (int cc = 0; cc < 8; ++cc) {
        body(2 * cc,     scA, scB);
        body(2 * cc + 1, scB, scA);
    }
}

// ---------------------------------------------------------------------------
// Kernel 2: MMA attention + gate + output projection, fused. Block = row i.
// 512 threads = 16 warps (4/SMSP); warp = (h, q-slot of 64), two 32-q units.
// ---------------------------------------------------------------------------
__global__ __launch_bounds__(512, 1) void attn_kernel(
    const float* __restrict__ Wo, const float* __restrict__ bo,
    float* __restrict__ out)
{
    extern __shared__ float smf[];
    u32* s_kw = (u32*)smf;                              // 8192 u32 = 32 KB
    __half* s_vt = (__half*)(smf + 8192);               // 64 rows x 264 fp16
    const u32* s_vw = (const u32*)(smf + 8192);
    // epilogue aliases (after sync):
    float* s_goT = smf;             // [64][260]
    float* s_wo  = smf + 16640;     // 4096
    float* s_bo  = smf + 20736;     // 64

    const int i = blockIdx.x;
    const int tid = threadIdx.x;
    const int w = tid >> 5, lane = tid & 31;
    const int h = w & 3, qslot = w >> 2;   // qslot 0..3
    const int g = lane >> 2, t = lane & 3;

    // ---- stage K (fp16 pairs) and V^T (fp16, transposed) ----
    {
        const float4* gk4 = (const float4*)(g_k + i * 16384);
        const float4* gv4 = (const float4*)(g_v + i * 16384);
        #pragma unroll
        for (int it = 0; it < 8; ++it) {
            const int idx = it * 512 + tid;
            const int key = idx >> 4, f4 = idx & 15;
            const int hh = f4 >> 2, quad = f4 & 3;
            float4 kv = gk4[idx];
            const int ka = (hh * 256 + key) * 8 + quad * 2;
            s_kw[ka]     = hpack(kv.x, kv.y);
            s_kw[ka + 1] = hpack(kv.z, kv.w);
            float4 vv = gv4[idx];
            float ve[4] = {vv.x, vv.y, vv.z, vv.w};
            #pragma unroll
            for (int e = 0; e < 4; ++e) {
                const int dl = hh * 16 + quad * 4 + e;
                s_vt[dl * 264 + key] = __float2half_rn(ve[e]);
            }
        }
    }
    __syncthreads();

    float oc[2][2][2][4];
    float inv[2][2][2];
    #pragma unroll 1
    for (int u = 0; u < 2; ++u) {
        const int q0 = qslot * 64 + u * 32;
        float ls[2][2];
        run_unit(i, h, q0, g, t, s_kw, s_vw, oc[u], ls);
        #pragma unroll
        for (int mt = 0; mt < 2; ++mt)
            #pragma unroll
            for (int rr = 0; rr < 2; ++rr) {
                float v = ls[mt][rr];
                v += __shfl_xor_sync(0xffffffffu, v, 1);
                v += __shfl_xor_sync(0xffffffffu, v, 2);
                inv[u][mt][rr] = 1.0f / v;
            }
    }

    // normalize + gate (registers only)
    {
        const float2* gp = (const float2*)g_gate;
        #pragma unroll
        for (int u = 0; u < 2; ++u) {
            const int q0 = qslot * 64 + u * 32;
            #pragma unroll
            for (int mt = 0; mt < 2; ++mt) {
                const int qr = i * 256 + q0 + mt * 16 + g;
                #pragma unroll
                for (int nd = 0; nd < 2; ++nd) {
                    float2 g0 = gp[qr * 32 + h * 8 + nd * 4 + t];
                    float2 g1 = gp[(qr + 8) * 32 + h * 8 + nd * 4 + t];
                    oc[u][mt][nd][0] *= inv[u][mt][0] * g0.x;
                    oc[u][mt][nd][1] *= inv[u][mt][0] * g0.y;
                    oc[u][mt][nd][2] *= inv[u][mt][1] * g1.x;
                    oc[u][mt][nd][3] *= inv[u][mt][1] * g1.y;
                }
            }
        }
    }

    __syncthreads();   // all K/V smem reads done; re-use as goT

    // write goT [d][q] stride 260
    #pragma unroll
    for (int u = 0; u < 2; ++u) {
        const int q0 = qslot * 64 + u * 32;
        #pragma unroll
        for (int mt = 0; mt < 2; ++mt) {
            const int qr = q0 + mt * 16 + g;
            #pragma unroll
            for (int nd = 0; nd < 2; ++nd) {
                const int d0 = h * 16 + nd * 8 + 2 * t;
                s_goT[d0 * 260 + qr]           = oc[u][mt][nd][0];
                s_goT[(d0 + 1) * 260 + qr]     = oc[u][mt][nd][1];
                s_goT[d0 * 260 + qr + 8]       = oc[u][mt][nd][2];
                s_goT[(d0 + 1) * 260 + qr + 8] = oc[u][mt][nd][3];
            }
        }
    }
    for (int idx = tid; idx < 4096; idx += 512) s_wo[idx] = Wo[idx];
    if (tid < 64) s_bo[tid] = bo[tid];
    __syncthreads();

    // out = go @ Wo + bo : thread = (col jj, 32-q group pz)
    const int jj = tid & 63;
    const int pz = tid >> 6;    // 0..7
    u64 oa[16];
    #pragma unroll
    for (int m = 0; m < 16; ++m) oa[m] = 0ull;
    #pragma unroll 4
    for (int d = 0; d < 64; ++d) {
        const u64 w2 = dup2(s_wo[d * 64 + jj]);
        const u64* gpt = (const u64*)(s_goT + d * 260 + pz * 32);
        #pragma unroll
        for (int m = 0; m < 16; ++m) fma2(oa[m], gpt[m], w2);
    }
    const float bov = s_bo[jj];
    float* op = out + (i * 256 + pz * 32) * 64 + jj;
    #pragma unroll
    for (int m = 0; m < 16; ++m) {
        float lo, hi;
        unpack2(oa[m], lo, hi);
        op[(2 * m) * 64]     = lo + bov;
        op[(2 * m + 1) * 64] = hi + bov;
    }
}

// ---------------------------------------------------------------------------
extern "C" void kernel_launch(void* const* d_in, const int* in_sizes, int n_in,
                              void* d_out, int out_size)
{
    const float* x    = (const float*)d_in[0];
    const int*   mask = (const int*)d_in[1];
    const float* ln_s = (const float*)d_in[2];
    const float* ln_b = (const float*)d_in[3];
    const float* Wq   = (const float*)d_in[4];
    const float* Wk   = (const float*)d_in[5];
    const float* Wv   = (const float*)d_in[6];
    const float* Wg   = (const float*)d_in[7];
    const float* bg   = (const float*)d_in[8];
    const float* Wb   = (const float*)d_in[9];
    const float* Wo   = (const float*)d_in[10];
    const float* bo   = (const float*)d_in[11];
    float* out = (float*)d_out;
    (void)in_sizes; (void)n_in; (void)out_size;

    const int sm1 = (4 * 4096 + 256 + 64 * 66 + 3 * 64) * (int)sizeof(float);
    const int sm2 = 20800 * (int)sizeof(float);   // 83,200 B (staging 66.5 KB fits inside)
    cudaFuncSetAttribute(proj_kernel, cudaFuncAttributeMaxDynamicSharedMemorySize, sm1);
    cudaFuncSetAttribute(attn_kernel, cudaFuncAttributeMaxDynamicSharedMemorySize, sm2);

    proj_kernel<<<296, 256, sm1>>>(x, mask, ln_s, ln_b, Wq, Wk, Wv, Wg, bg, Wb);
    attn_kernel<<<256, 512, sm2>>>(Wo, bo, out);
}

// round 15
// speedup vs baseline: 1.2259x; 1.0106x over previous
#include <cuda_runtime.h>
#include <cuda_fp16.h>
#include <math.h>
#include <string.h>

#define NSEQ 256
#define DIM 64
#define NH 4
#define NPOS (NSEQ * NSEQ)
#define NEGINF -1000000000.0f
#define LOG2E 1.4426950408889634f

typedef unsigned long long u64;
typedef unsigned int u32;

// ---- packed fp32x2 helpers (proj + epilogue) ----
__device__ __forceinline__ u64 pack2(float lo, float hi) {
    u64 r; asm("mov.b64 %0, {%1, %2};" : "=l"(r) : "f"(lo), "f"(hi)); return r;
}
__device__ __forceinline__ u64 dup2(float v) { return pack2(v, v); }
__device__ __forceinline__ void unpack2(u64 v, float& lo, float& hi) {
    asm("mov.b64 {%0, %1}, %2;" : "=f"(lo), "=f"(hi) : "l"(v));
}
__device__ __forceinline__ void fma2(u64& d, u64 a, u64 b) {
    asm("fma.rn.f32x2 %0, %1, %2, %0;" : "+l"(d) : "l"(a), "l"(b));
}
__device__ __forceinline__ u64 mul2(u64 a, u64 b) {
    u64 r; asm("mul.rn.f32x2 %0, %1, %2;" : "=l"(r) : "l"(a), "l"(b)); return r;
}

// pack two floats as fp16x2 (low half = a)
__device__ __forceinline__ u32 hpack(float a, float b) {
    __half2 p = __floats2half2_rn(a, b);
    u32 r; memcpy(&r, &p, 4); return r;
}

__device__ __forceinline__ float ex2f(float x) {
    float r; asm("ex2.approx.f32 %0, %1;" : "=f"(r) : "f"(x)); return r;
}

// mma.sync m16n8k16 row.col f32.f16.f16.f32, D = A*B + D
__device__ __forceinline__ void mma16816(float* c, const u32* a, const u32* b) {
    asm volatile(
        "mma.sync.aligned.m16n8k16.row.col.f32.f16.f16.f32 "
        "{%0,%1,%2,%3}, {%4,%5,%6,%7}, {%8,%9}, {%0,%1,%2,%3};"
        : "+f"(c[0]), "+f"(c[1]), "+f"(c[2]), "+f"(c[3])
        : "r"(a[0]), "r"(a[1]), "r"(a[2]), "r"(a[3]), "r"(b[0]), "r"(b[1]));
}

__device__ __forceinline__ void ldsm_x4(u32& r0, u32& r1, u32& r2, u32& r3, u32 addr) {
    asm volatile("ldmatrix.sync.aligned.m8n8.x4.shared.b16 {%0,%1,%2,%3}, [%4];"
                 : "=r"(r0), "=r"(r1), "=r"(r2), "=r"(r3) : "r"(addr));
}
__device__ __forceinline__ void ldsm_x4_t(u32& r0, u32& r1, u32& r2, u32& r3, u32 addr) {
    asm volatile("ldmatrix.sync.aligned.m8n8.x4.trans.shared.b16 {%0,%1,%2,%3}, [%4];"
                 : "=r"(r0), "=r"(r1), "=r"(r2), "=r"(r3) : "r"(addr));
}

// Scratch
__device__ float g_q[NPOS * DIM];
__device__ float g_k[NPOS * DIM];
__device__ float g_v[NPOS * DIM];
__device__ float g_gate[NPOS * DIM];
__device__ float g_bm[NH * NSEQ * NSEQ];   // [h][q][k], pre-scaled by log2(e)

// ---------------------------------------------------------------------------
// Kernel 1 (persistent): LayerNorm + Q/K/V/Gate projections + fused bias/mask.
// ---------------------------------------------------------------------------
__global__ __launch_bounds__(256, 2) void proj_kernel(
    const float* __restrict__ x, const int* __restrict__ mask,
    const float* __restrict__ ln_s, const float* __restrict__ ln_b,
    const float* __restrict__ Wq, const float* __restrict__ Wk,
    const float* __restrict__ Wv, const float* __restrict__ Wg,
    const float* __restrict__ bg, const float* __restrict__ Wb)
{
    extern __shared__ float sm[];
    float* s_wq = sm;                 // 4096
    float* s_wk = s_wq + 4096;
    float* s_wv = s_wk + 4096;
    float* s_wg = s_wv + 4096;
    float* s_wb = s_wg + 4096;        // 256
    float* s_xt = s_wb + 256;         // [d][pos] stride 66
    float* s_bg = s_xt + 64 * 66;
    float* s_ls = s_bg + 64;
    float* s_lb = s_ls + 64;

    const int tid = threadIdx.x;
    for (int idx = tid; idx < 4096; idx += 256) {
        s_wq[idx] = Wq[idx];
        s_wk[idx] = Wk[idx];
        s_wv[idx] = Wv[idx];
        s_wg[idx] = Wg[idx];
    }
    s_wb[tid] = Wb[tid];
    if (tid < 64) { s_bg[tid] = bg[tid]; s_ls[tid] = ln_s[tid]; s_lb[tid] = ln_b[tid]; }
    __syncthreads();

    const int lane = tid & 31;
    const int wrp  = tid >> 5;
    const int jj   = tid & 63;
    const int pz   = tid >> 6;
    const int ph   = tid >> 2;
    const int hh   = tid & 3;

    for (int c = blockIdx.x; c < 1024; c += gridDim.x) {
        const int p0 = c * 64;

        for (int pp = wrp; pp < 64; pp += 8) {
            const float* xr = x + (p0 + pp) * DIM;
            float a = xr[lane];
            float b = xr[lane + 32];
            float sum = a + b;
            float sq = a * a + b * b;
            #pragma unroll
            for (int off = 16; off > 0; off >>= 1) {
                sum += __shfl_xor_sync(0xffffffffu, sum, off);
                sq  += __shfl_xor_sync(0xffffffffu, sq, off);
            }
            float mu  = sum * (1.0f / 64.0f);
            float var = sq * (1.0f / 64.0f) - mu * mu;
            float inv = rsqrtf(var + 1e-5f);
            s_xt[lane * 66 + pp]        = (a - mu) * inv * s_ls[lane]      + s_lb[lane];
            s_xt[(lane + 32) * 66 + pp] = (b - mu) * inv * s_ls[lane + 32] + s_lb[lane + 32];
        }
        __syncthreads();

        // bias + mask -> g_bm[h][q][k]  (pre-scaled by log2(e) for ex2)
        {
            float acc = 0.0f;
            #pragma unroll 8
            for (int d = 0; d < 64; ++d)
                acc = fmaf(s_xt[d * 66 + ph], s_wb[d * 4 + hh], acc);
            const int flat = p0 + ph;
            const int r = flat >> 8;    // q
            const int cc = flat & 255;  // k
            g_bm[hh * 65536 + r * 256 + cc] = (mask[flat] != 0) ? acc * LOG2E : NEGINF;
        }

        u64 aq[8], ak[8], av[8], ag[8];
        #pragma unroll
        for (int m = 0; m < 8; ++m) { aq[m] = 0ull; ak[m] = 0ull; av[m] = 0ull; ag[m] = 0ull; }

        #pragma unroll 2
        for (int d = 0; d < 64; ++d) {
            const u64 wq2 = dup2(s_wq[d * 64 + jj]);
            const u64 wk2 = dup2(s_wk[d * 64 + jj]);
            const u64 wv2 = dup2(s_wv[d * 64 + jj]);
            const u64 wg2 = dup2(s_wg[d * 64 + jj]);
            const u64* xp = (const u64*)(s_xt + d * 66 + pz * 16);
            #pragma unroll
            for (int m = 0; m < 8; ++m) {
                const u64 xv = xp[m];
                fma2(aq[m], xv, wq2);
                fma2(ak[m], xv, wk2);
                fma2(av[m], xv, wv2);
                fma2(ag[m], xv, wg2);
            }
        }

        #pragma unroll
        for (int m = 0; m < 8; ++m) {
            const int o = (p0 + pz * 16 + 2 * m) * 64 + jj;
            float v0, v1;
            unpack2(aq[m], v0, v1); g_q[o] = v0; g_q[o + 64] = v1;
            unpack2(ak[m], v0, v1); g_k[o] = v0; g_k[o + 64] = v1;
            unpack2(av[m], v0, v1); g_v[o] = v0; g_v[o + 64] = v1;
            unpack2(ag[m], v0, v1);
            g_gate[o]      = 1.0f / (1.0f + __expf(-(v0 + s_bg[jj])));
            g_gate[o + 64] = 1.0f / (1.0f + __expf(-(v1 + s_bg[jj])));
        }
        __syncthreads();
    }
}

// ---------------------------------------------------------------------------
// Attention unit: warp computes O[32 q][16 d] + row sums for (i, h, q0).
// K/V fragments via ldmatrix from 48B-pitch [h][key][d] tiles (conflict-free).
// Bias double-buffer lives IN the S accumulators (scA/scB alternate).
// ---------------------------------------------------------------------------
__device__ __forceinline__ void run_unit(
    int i, int h, int q0, int g, int t,
    u32 kaddr0, u32 vaddr0,
    float oc[2][2][4], float ls[2][2])
{
    // Q frags (pre-scaled by 1/sqrt(16) * log2(e))
    u32 qa[2][4];
    {
        const float2* qp = (const float2*)g_q;
        const float qs = 0.25f * LOG2E;
        #pragma unroll
        for (int mt = 0; mt < 2; ++mt) {
            const int r0 = i * 256 + q0 + mt * 16 + g;
            float2 f0 = qp[r0 * 32 + h * 8 + t];
            float2 f1 = qp[(r0 + 8) * 32 + h * 8 + t];
            float2 f2 = qp[r0 * 32 + h * 8 + 4 + t];
            float2 f3 = qp[(r0 + 8) * 32 + h * 8 + 4 + t];
            qa[mt][0] = hpack(f0.x * qs, f0.y * qs);
            qa[mt][1] = hpack(f1.x * qs, f1.y * qs);
            qa[mt][2] = hpack(f2.x * qs, f2.y * qs);
            qa[mt][3] = hpack(f3.x * qs, f3.y * qs);
        }
    }
    #pragma unroll
    for (int mt = 0; mt < 2; ++mt) {
        ls[mt][0] = 0.f; ls[mt][1] = 0.f;
        #pragma unroll
        for (int nd = 0; nd < 2; ++nd)
            #pragma unroll
            for (int r = 0; r < 4; ++r) oc[mt][nd][r] = 0.f;
    }

    const float2* bp = (const float2*)g_bm + h * 32768 + (q0 + g) * 128 + t;

    float scA[2][2][4], scB[2][2][4];

    // prologue: bias chunk 0 -> scA
    #pragma unroll
    for (int mt = 0; mt < 2; ++mt)
        #pragma unroll
        for (int nt = 0; nt < 2; ++nt) {
            float2 b0 = __ldg(bp + mt * 2048 + nt * 4);
            float2 b1 = __ldg(bp + mt * 2048 + 1024 + nt * 4);
            scA[mt][nt][0] = b0.x; scA[mt][nt][1] = b0.y;
            scA[mt][nt][2] = b1.x; scA[mt][nt][3] = b1.y;
        }

    auto body = [&](int c, float sc[2][2][4], float scP[2][2][4]) {
        // K frags: one ldmatrix.x4 (r0=b0/nt0, r1=b1/nt0, r2=b0/nt1, r3=b1/nt1)
        u32 k0, k1, k2, k3;
        ldsm_x4(k0, k1, k2, k3, kaddr0 + c * 768);
        // QK MMA into sc (already holds bias)
        {
            u32 b0[2] = {k0, k1}, b1[2] = {k2, k3};
            #pragma unroll
            for (int mt = 0; mt < 2; ++mt) {
                mma16816(sc[mt][0], qa[mt], b0);
                mma16816(sc[mt][1], qa[mt], b1);
            }
        }
        // prefetch bias for chunk c+1 straight into scP
        if (c < 15) {
            #pragma unroll
            for (int mt = 0; mt < 2; ++mt)
                #pragma unroll
                for (int nt = 0; nt < 2; ++nt) {
                    float2 b0 = __ldg(bp + mt * 2048 + (c + 1) * 8 + nt * 4);
                    float2 b1 = __ldg(bp + mt * 2048 + 1024 + (c + 1) * 8 + nt * 4);
                    scP[mt][nt][0] = b0.x; scP[mt][nt][1] = b0.y;
                    scP[mt][nt][2] = b1.x; scP[mt][nt][3] = b1.y;
                }
        }
        // exp2 + row sums + P frags
        u32 pa[2][4];
        #pragma unroll
        for (int mt = 0; mt < 2; ++mt) {
            float e00 = ex2f(sc[mt][0][0]);
            float e01 = ex2f(sc[mt][0][1]);
            float e02 = ex2f(sc[mt][0][2]);
            float e03 = ex2f(sc[mt][0][3]);
            float e10 = ex2f(sc[mt][1][0]);
            float e11 = ex2f(sc[mt][1][1]);
            float e12 = ex2f(sc[mt][1][2]);
            float e13 = ex2f(sc[mt][1][3]);
            ls[mt][0] += (e00 + e01) + (e10 + e11);
            ls[mt][1] += (e02 + e03) + (e12 + e13);
            pa[mt][0] = hpack(e00, e01);
            pa[mt][1] = hpack(e02, e03);
            pa[mt][2] = hpack(e10, e11);
            pa[mt][3] = hpack(e12, e13);
        }
        // V frags: one ldmatrix.x4.trans (r0=b0/nd0, r1=b1/nd0, r2=b0/nd1, r3=b1/nd1)
        u32 v0, v1, v2, v3;
        ldsm_x4_t(v0, v1, v2, v3, vaddr0 + c * 768);
        {
            u32 b0[2] = {v0, v1}, b1[2] = {v2, v3};
            #pragma unroll
            for (int mt = 0; mt < 2; ++mt) {
                mma16816(oc[mt][0], pa[mt], b0);
                mma16816(oc[mt][1], pa[mt], b1);
            }
        }
    };

    #pragma unroll 1
    for (int cc = 0; cc < 8; ++cc) {
        body(2 * cc,     scA, scB);
        body(2 * cc + 1, scB, scA);
    }
}

// ---------------------------------------------------------------------------
// Kernel 2: MMA attention + gate + output projection, fused. Block = row i.
// 512 threads = 16 warps (4/SMSP); warp = (h, q-slot of 64), two 32-q units.
// K/V in smem as [h][256 keys][24 halfs] (48B pitch, ldmatrix-friendly).
// ---------------------------------------------------------------------------
__global__ __launch_bounds__(512, 1) void attn_kernel(
    const float* __restrict__ Wo, const float* __restrict__ bo,
    float* __restrict__ out)
{
    extern __shared__ float smf[];
    u32* s_k32 = (u32*)smf;            // 12288 u32 = 48 KB (pitch 12 u32/key)
    u32* s_v32 = s_k32 + 12288;        // 48 KB
    // epilogue aliases (after sync):
    float* s_goT = smf;                // [64][260] = 66560 B
    float* s_wo  = smf + 16640;        // 4096 f
    float* s_bo  = smf + 20736;        // 64 f

    const int i = blockIdx.x;
    const int tid = threadIdx.x;
    const int w = tid >> 5, lane = tid & 31;
    const int h = w & 3, qslot = w >> 2;   // qslot 0..3
    const int g = lane >> 2, t = lane & 3;

    // ---- stage K and V as fp16 [h][key][16 d], pitch 24 halfs ----
    {
        const float4* gk4 = (const float4*)(g_k + i * 16384);
        const float4* gv4 = (const float4*)(g_v + i * 16384);
        #pragma unroll
        for (int it = 0; it < 8; ++it) {
            const int idx = it * 512 + tid;
            const int key = idx >> 4, f4 = idx & 15;
            const int hh = f4 >> 2, quad = f4 & 3;
            const int base = (hh * 256 + key) * 12 + quad * 2;
            float4 kv = gk4[idx];
            s_k32[base]     = hpack(kv.x, kv.y);
            s_k32[base + 1] = hpack(kv.z, kv.w);
            float4 vv = gv4[idx];
            s_v32[base]     = hpack(vv.x, vv.y);
            s_v32[base + 1] = hpack(vv.z, vv.w);
        }
    }

    // ldmatrix lane addresses (bytes, shared space)
    u32 sbase;
    asm("{ .reg .u64 tt; cvta.to.shared.u64 tt, %1; cvt.u32.u64 %0, tt; }"
        : "=r"(sbase) : "l"(smf));
    const int rK = (lane & 7) + ((lane >> 4) & 1) * 8;
    const int dK = ((lane >> 3) & 1) * 8;
    const int rV = (lane & 7) + ((lane >> 3) & 1) * 8;
    const int dV = ((lane >> 4) & 1) * 8;
    const u32 kaddr0 = sbase + ((h * 256 + rK) * 24 + dK) * 2;
    const u32 vaddr0 = sbase + 49152 + ((h * 256 + rV) * 24 + dV) * 2;

    __syncthreads();

    float oc[2][2][2][4];
    float inv[2][2][2];
    #pragma unroll 1
    for (int u = 0; u < 2; ++u) {
        const int q0 = qslot * 64 + u * 32;
        float ls[2][2];
        run_unit(i, h, q0, g, t, kaddr0, vaddr0, oc[u], ls);
        #pragma unroll
        for (int mt = 0; mt < 2; ++mt)
            #pragma unroll
            for (int rr = 0; rr < 2; ++rr) {
                float v = ls[mt][rr];
                v += __shfl_xor_sync(0xffffffffu, v, 1);
                v += __shfl_xor_sync(0xffffffffu, v, 2);
                inv[u][mt][rr] = 1.0f / v;
            }
    }

    // normalize + gate (registers only)
    {
        const float2* gp = (const float2*)g_gate;
        #pragma unroll
        for (int u = 0; u < 2; ++u) {
            const int q0 = qslot * 64 + u * 32;
            #pragma unroll
            for (int mt = 0; mt < 2; ++mt) {
                const int qr = i * 256 + q0 + mt * 16 + g;
                #pragma unroll
                for (int nd = 0; nd < 2; ++nd) {
                    float2 g0 = gp[qr * 32 + h * 8 + nd * 4 + t];
                    float2 g1 = gp[(qr + 8) * 32 + h * 8 + nd * 4 + t];
                    oc[u][mt][nd][0] *= inv[u][mt][0] * g0.x;
                    oc[u][mt][nd][1] *= inv[u][mt][0] * g0.y;
                    oc[u][mt][nd][2] *= inv[u][mt][1] * g1.x;
                    oc[u][mt][nd][3] *= inv[u][mt][1] * g1.y;
                }
            }
        }
    }

    __syncthreads();   // all K/V smem reads done; re-use as goT

    // write goT [d][q] stride 260
    #pragma unroll
    for (int u = 0; u < 2; ++u) {
        const int q0 = qslot * 64 + u * 32;
        #pragma unroll
        for (int mt = 0; mt < 2; ++mt) {
            const int qr = q0 + mt * 16 + g;
            #pragma unroll
            for (int nd = 0; nd < 2; ++nd) {
                const int d0 = h * 16 + nd * 8 + 2 * t;
                s_goT[d0 * 260 + qr]           = oc[u][mt][nd][0];
                s_goT[(d0 + 1) * 260 + qr]     = oc[u][mt][nd][1];
                s_goT[d0 * 260 + qr + 8]       = oc[u][mt][nd][2];
                s_goT[(d0 + 1) * 260 + qr + 8] = oc[u][mt][nd][3];
            }
        }
    }
    for (int idx = tid; idx < 4096; idx += 512) s_wo[idx] = Wo[idx];
    if (tid < 64) s_bo[tid] = bo[tid];
    __syncthreads();

    // out = go @ Wo + bo : thread = (col jj, 32-q group pz)
    const int jj = tid & 63;
    const int pz = tid >> 6;    // 0..7
    u64 oa[16];
    #pragma unroll
    for (int m = 0; m < 16; ++m) oa[m] = 0ull;
    #pragma unroll 4
    for (int d = 0; d < 64; ++d) {
        const u64 w2 = dup2(s_wo[d * 64 + jj]);
        const u64* gpt = (const u64*)(s_goT + d * 260 + pz * 32);
        #pragma unroll
        for (int m = 0; m < 16; ++m) fma2(oa[m], gpt[m], w2);
    }
    const float bov = s_bo[jj];
    float* op = out + (i * 256 + pz * 32) * 64 + jj;
    #pragma unroll
    for (int m = 0; m < 16; ++m) {
        float lo, hi;
        unpack2(oa[m], lo, hi);
        op[(2 * m) * 64]     = lo + bov;
        op[(2 * m + 1) * 64] = hi + bov;
    }
}

// ---------------------------------------------------------------------------
extern "C" void kernel_launch(void* const* d_in, const int* in_sizes, int n_in,
                              void* d_out, int out_size)
{
    const float* x    = (const float*)d_in[0];
    const int*   mask = (const int*)d_in[1];
    const float* ln_s = (const float*)d_in[2];
    const float* ln_b = (const float*)d_in[3];
    const float* Wq   = (const float*)d_in[4];
    const float* Wk   = (const float*)d_in[5];
    const float* Wv   = (const float*)d_in[6];
    const float* Wg   = (const float*)d_in[7];
    const float* bg   = (const float*)d_in[8];
    const float* Wb   = (const float*)d_in[9];
    const float* Wo   = (const float*)d_in[10];
    const float* bo   = (const float*)d_in[11];
    float* out = (float*)d_out;
    (void)in_sizes; (void)n_in; (void)out_size;

    const int sm1 = (4 * 4096 + 256 + 64 * 66 + 3 * 64) * (int)sizeof(float);
    const int sm2 = 98304;   // 48 KB K + 48 KB V (epilogue 83.2 KB aliases within)
    cudaFuncSetAttribute(proj_kernel, cudaFuncAttributeMaxDynamicSharedMemorySize, sm1);
    cudaFuncSetAttribute(attn_kernel, cudaFuncAttributeMaxDynamicSharedMemorySize, sm2);

    proj_kernel<<<296, 256, sm1>>>(x, mask, ln_s, ln_b, Wq, Wk, Wv, Wg, bg, Wb);
    attn_kernel<<<256, 512, sm2>>>(Wo, bo, out);
}

// round 16
// speedup vs baseline: 1.2622x; 1.0296x over previous
#include <cuda_runtime.h>
#include <cuda_fp16.h>
#include <math.h>
#include <string.h>

#define NSEQ 256
#define DIM 64
#define NH 4
#define NPOS (NSEQ * NSEQ)
#define NEGINF -1000000000.0f
#define LOG2E 1.4426950408889634f

typedef unsigned long long u64;
typedef unsigned int u32;

// ---- packed fp32x2 helpers (proj + epilogue) ----
__device__ __forceinline__ u64 pack2(float lo, float hi) {
    u64 r; asm("mov.b64 %0, {%1, %2};" : "=l"(r) : "f"(lo), "f"(hi)); return r;
}
__device__ __forceinline__ u64 dup2(float v) { return pack2(v, v); }
__device__ __forceinline__ void unpack2(u64 v, float& lo, float& hi) {
    asm("mov.b64 {%0, %1}, %2;" : "=f"(lo), "=f"(hi) : "l"(v));
}
__device__ __forceinline__ void fma2(u64& d, u64 a, u64 b) {
    asm("fma.rn.f32x2 %0, %1, %2, %0;" : "+l"(d) : "l"(a), "l"(b));
}
__device__ __forceinline__ u64 mul2(u64 a, u64 b) {
    u64 r; asm("mul.rn.f32x2 %0, %1, %2;" : "=l"(r) : "l"(a), "l"(b)); return r;
}

// pack two floats as fp16x2 (low half = a)
__device__ __forceinline__ u32 hpack(float a, float b) {
    __half2 p = __floats2half2_rn(a, b);
    u32 r; memcpy(&r, &p, 4); return r;
}

__device__ __forceinline__ float ex2f(float x) {
    float r; asm("ex2.approx.f32 %0, %1;" : "=f"(r) : "f"(x)); return r;
}

// mma.sync m16n8k16 row.col f32.f16.f16.f32, D = A*B + D
__device__ __forceinline__ void mma16816(float* c, const u32* a, const u32* b) {
    asm volatile(
        "mma.sync.aligned.m16n8k16.row.col.f32.f16.f16.f32 "
        "{%0,%1,%2,%3}, {%4,%5,%6,%7}, {%8,%9}, {%0,%1,%2,%3};"
        : "+f"(c[0]), "+f"(c[1]), "+f"(c[2]), "+f"(c[3])
        : "r"(a[0]), "r"(a[1]), "r"(a[2]), "r"(a[3]), "r"(b[0]), "r"(b[1]));
}

__device__ __forceinline__ void ldsm_x4(u32& r0, u32& r1, u32& r2, u32& r3, u32 addr) {
    asm volatile("ldmatrix.sync.aligned.m8n8.x4.shared.b16 {%0,%1,%2,%3}, [%4];"
                 : "=r"(r0), "=r"(r1), "=r"(r2), "=r"(r3) : "r"(addr));
}
__device__ __forceinline__ void ldsm_x4_t(u32& r0, u32& r1, u32& r2, u32& r3, u32 addr) {
    asm volatile("ldmatrix.sync.aligned.m8n8.x4.trans.shared.b16 {%0,%1,%2,%3}, [%4];"
                 : "=r"(r0), "=r"(r1), "=r"(r2), "=r"(r3) : "r"(addr));
}

// Scratch
__device__ float g_q[NPOS * DIM];
__device__ float g_k[NPOS * DIM];
__device__ float g_v[NPOS * DIM];
__device__ float g_gate[NPOS * DIM];
// bias+mask in MMA C-fragment order:
// float4 index = (h*8 + qtile)*2048 + chunk*128 + part*32 + (g*4 + t)
//   qtile = q>>5, chunk = k>>4, part = ((q>>4)&1)*2 + ((q>>3)&1)
//   within float4: nt*2 + (k&1),  nt = (k>>3)&1
__device__ float g_bm[NH * NSEQ * NSEQ];

// ---------------------------------------------------------------------------
// Kernel 1 (persistent): LayerNorm + Q/K/V/Gate projections + fused bias/mask.
// ---------------------------------------------------------------------------
__global__ __launch_bounds__(256, 2) void proj_kernel(
    const float* __restrict__ x, const int* __restrict__ mask,
    const float* __restrict__ ln_s, const float* __restrict__ ln_b,
    const float* __restrict__ Wq, const float* __restrict__ Wk,
    const float* __restrict__ Wv, const float* __restrict__ Wg,
    const float* __restrict__ bg, const float* __restrict__ Wb)
{
    extern __shared__ float sm[];
    float* s_wq = sm;                 // 4096
    float* s_wk = s_wq + 4096;
    float* s_wv = s_wk + 4096;
    float* s_wg = s_wv + 4096;
    float* s_wb = s_wg + 4096;        // 256
    float* s_xt = s_wb + 256;         // [d][pos] stride 66
    float* s_bg = s_xt + 64 * 66;
    float* s_ls = s_bg + 64;
    float* s_lb = s_ls + 64;

    const int tid = threadIdx.x;
    for (int idx = tid; idx < 4096; idx += 256) {
        s_wq[idx] = Wq[idx];
        s_wk[idx] = Wk[idx];
        s_wv[idx] = Wv[idx];
        s_wg[idx] = Wg[idx];
    }
    s_wb[tid] = Wb[tid];
    if (tid < 64) { s_bg[tid] = bg[tid]; s_ls[tid] = ln_s[tid]; s_lb[tid] = ln_b[tid]; }
    __syncthreads();

    const int lane = tid & 31;
    const int wrp  = tid >> 5;
    const int jj   = tid & 63;
    const int pz   = tid >> 6;
    const int ph   = tid >> 2;
    const int hh   = tid & 3;

    for (int c = blockIdx.x; c < 1024; c += gridDim.x) {
        const int p0 = c * 64;

        for (int pp = wrp; pp < 64; pp += 8) {
            const float* xr = x + (p0 + pp) * DIM;
            float a = xr[lane];
            float b = xr[lane + 32];
            float sum = a + b;
            float sq = a * a + b * b;
            #pragma unroll
            for (int off = 16; off > 0; off >>= 1) {
                sum += __shfl_xor_sync(0xffffffffu, sum, off);
                sq  += __shfl_xor_sync(0xffffffffu, sq, off);
            }
            float mu  = sum * (1.0f / 64.0f);
            float var = sq * (1.0f / 64.0f) - mu * mu;
            float inv = rsqrtf(var + 1e-5f);
            s_xt[lane * 66 + pp]        = (a - mu) * inv * s_ls[lane]      + s_lb[lane];
            s_xt[(lane + 32) * 66 + pp] = (b - mu) * inv * s_ls[lane + 32] + s_lb[lane + 32];
        }
        __syncthreads();

        // bias + mask -> g_bm in MMA fragment order (pre-scaled by log2 e)
        {
            float acc = 0.0f;
            #pragma unroll 8
            for (int d = 0; d < 64; ++d)
                acc = fmaf(s_xt[d * 66 + ph], s_wb[d * 4 + hh], acc);
            const int flat = p0 + ph;
            const int r  = flat >> 8;    // q
            const int cc = flat & 255;   // k
            const float val = (mask[flat] != 0) ? acc * LOG2E : NEGINF;
            const int qtile = r >> 5;
            const int gg    = r & 7;
            const int part  = ((r >> 4) & 1) * 2 + ((r >> 3) & 1);
            const int chunk = cc >> 4;
            const int nt    = (cc >> 3) & 1;
            const int tt    = (cc >> 1) & 3;
            const int e     = cc & 1;
            const int f4    = (hh * 8 + qtile) * 2048 + chunk * 128 + part * 32 + gg * 4 + tt;
            g_bm[f4 * 4 + nt * 2 + e] = val;
        }

        u64 aq[8], ak[8], av[8], ag[8];
        #pragma unroll
        for (int m = 0; m < 8; ++m) { aq[m] = 0ull; ak[m] = 0ull; av[m] = 0ull; ag[m] = 0ull; }

        #pragma unroll 2
        for (int d = 0; d < 64; ++d) {
            const u64 wq2 = dup2(s_wq[d * 64 + jj]);
            const u64 wk2 = dup2(s_wk[d * 64 + jj]);
            const u64 wv2 = dup2(s_wv[d * 64 + jj]);
            const u64 wg2 = dup2(s_wg[d * 64 + jj]);
            const u64* xp = (const u64*)(s_xt + d * 66 + pz * 16);
            #pragma unroll
            for (int m = 0; m < 8; ++m) {
                const u64 xv = xp[m];
                fma2(aq[m], xv, wq2);
                fma2(ak[m], xv, wk2);
                fma2(av[m], xv, wv2);
                fma2(ag[m], xv, wg2);
            }
        }

        #pragma unroll
        for (int m = 0; m < 8; ++m) {
            const int o = (p0 + pz * 16 + 2 * m) * 64 + jj;
            float v0, v1;
            unpack2(aq[m], v0, v1); g_q[o] = v0; g_q[o + 64] = v1;
            unpack2(ak[m], v0, v1); g_k[o] = v0; g_k[o + 64] = v1;
            unpack2(av[m], v0, v1); g_v[o] = v0; g_v[o + 64] = v1;
            unpack2(ag[m], v0, v1);
            g_gate[o]      = 1.0f / (1.0f + __expf(-(v0 + s_bg[jj])));
            g_gate[o + 64] = 1.0f / (1.0f + __expf(-(v1 + s_bg[jj])));
        }
        __syncthreads();
    }
}

// ---------------------------------------------------------------------------
// Attention unit: warp computes O[32 q][16 d] + row sums for (i, h, q0).
// K/V fragments via ldmatrix; bias via 4 coalesced LDG.128 per chunk.
// ---------------------------------------------------------------------------
__device__ __forceinline__ void run_unit(
    int i, int h, int q0, int g, int t,
    u32 kaddr0, u32 vaddr0,
    float oc[2][2][4], float ls[2][2])
{
    // Q frags (pre-scaled by 1/sqrt(16) * log2(e))
    u32 qa[2][4];
    {
        const float2* qp = (const float2*)g_q;
        const float qs = 0.25f * LOG2E;
        #pragma unroll
        for (int mt = 0; mt < 2; ++mt) {
            const int r0 = i * 256 + q0 + mt * 16 + g;
            float2 f0 = qp[r0 * 32 + h * 8 + t];
            float2 f1 = qp[(r0 + 8) * 32 + h * 8 + t];
            float2 f2 = qp[r0 * 32 + h * 8 + 4 + t];
            float2 f3 = qp[(r0 + 8) * 32 + h * 8 + 4 + t];
            qa[mt][0] = hpack(f0.x * qs, f0.y * qs);
            qa[mt][1] = hpack(f1.x * qs, f1.y * qs);
            qa[mt][2] = hpack(f2.x * qs, f2.y * qs);
            qa[mt][3] = hpack(f3.x * qs, f3.y * qs);
        }
    }
    #pragma unroll
    for (int mt = 0; mt < 2; ++mt) {
        ls[mt][0] = 0.f; ls[mt][1] = 0.f;
        #pragma unroll
        for (int nd = 0; nd < 2; ++nd)
            #pragma unroll
            for (int r = 0; r < 4; ++r) oc[mt][nd][r] = 0.f;
    }

    // bias fragment base: float4 ptr for this (h, qtile), lane g*4+t
    const float4* bp = (const float4*)g_bm + (h * 8 + (q0 >> 5)) * 2048 + (g * 4 + t);

    float scA[2][2][4], scB[2][2][4];

    // prologue: bias chunk 0 -> scA
    #pragma unroll
    for (int mt = 0; mt < 2; ++mt)
        #pragma unroll
        for (int rrh = 0; rrh < 2; ++rrh) {
            float4 f = __ldg(bp + (mt * 2 + rrh) * 32);
            scA[mt][0][rrh * 2 + 0] = f.x; scA[mt][0][rrh * 2 + 1] = f.y;
            scA[mt][1][rrh * 2 + 0] = f.z; scA[mt][1][rrh * 2 + 1] = f.w;
        }

    auto body = [&](int c, float sc[2][2][4], float scP[2][2][4]) {
        // K frags: one ldmatrix.x4 ; V frags issued early to overlap
        u32 k0, k1, k2, k3;
        ldsm_x4(k0, k1, k2, k3, kaddr0 + c * 768);
        u32 v0, v1, v2, v3;
        ldsm_x4_t(v0, v1, v2, v3, vaddr0 + c * 768);
        // QK MMA into sc (already holds bias)
        {
            u32 b0[2] = {k0, k1}, b1[2] = {k2, k3};
            #pragma unroll
            for (int mt = 0; mt < 2; ++mt) {
                mma16816(sc[mt][0], qa[mt], b0);
                mma16816(sc[mt][1], qa[mt], b1);
            }
        }
        // prefetch bias for chunk c+1 straight into scP (4 coalesced LDG.128)
        if (c < 15) {
            #pragma unroll
            for (int mt = 0; mt < 2; ++mt)
                #pragma unroll
                for (int rrh = 0; rrh < 2; ++rrh) {
                    float4 f = __ldg(bp + (c + 1) * 128 + (mt * 2 + rrh) * 32);
                    scP[mt][0][rrh * 2 + 0] = f.x; scP[mt][0][rrh * 2 + 1] = f.y;
                    scP[mt][1][rrh * 2 + 0] = f.z; scP[mt][1][rrh * 2 + 1] = f.w;
                }
        }
        // exp2 + row sums + P frags
        u32 pa[2][4];
        #pragma unroll
        for (int mt = 0; mt < 2; ++mt) {
            float e00 = ex2f(sc[mt][0][0]);
            float e01 = ex2f(sc[mt][0][1]);
            float e02 = ex2f(sc[mt][0][2]);
            float e03 = ex2f(sc[mt][0][3]);
            float e10 = ex2f(sc[mt][1][0]);
            float e11 = ex2f(sc[mt][1][1]);
            float e12 = ex2f(sc[mt][1][2]);
            float e13 = ex2f(sc[mt][1][3]);
            ls[mt][0] += (e00 + e01) + (e10 + e11);
            ls[mt][1] += (e02 + e03) + (e12 + e13);
            pa[mt][0] = hpack(e00, e01);
            pa[mt][1] = hpack(e02, e03);
            pa[mt][2] = hpack(e10, e11);
            pa[mt][3] = hpack(e12, e13);
        }
        // PV MMAs
        {
            u32 b0[2] = {v0, v1}, b1[2] = {v2, v3};
            #pragma unroll
            for (int mt = 0; mt < 2; ++mt) {
                mma16816(oc[mt][0], pa[mt], b0);
                mma16816(oc[mt][1], pa[mt], b1);
            }
        }
    };

    #pragma unroll 1
    for (int cc = 0; cc < 8; ++cc) {
        body(2 * cc,     scA, scB);
        body(2 * cc + 1, scB, scA);
    }
}

// ---------------------------------------------------------------------------
// Kernel 2: MMA attention + gate + output projection, fused. Block = row i.
// 512 threads = 16 warps (4/SMSP); warp = (h, q-slot of 64), two 32-q units.
// K/V in smem as [h][256 keys][24 halfs] (48B pitch, ldmatrix-friendly).
// ---------------------------------------------------------------------------
__global__ __launch_bounds__(512, 1) void attn_kernel(
    const float* __restrict__ Wo, const float* __restrict__ bo,
    float* __restrict__ out)
{
    extern __shared__ float smf[];
    u32* s_k32 = (u32*)smf;            // 12288 u32 = 48 KB (pitch 12 u32/key)
    u32* s_v32 = s_k32 + 12288;        // 48 KB
    // epilogue aliases (after sync):
    float* s_goT = smf;                // [64][260] = 66560 B
    float* s_wo  = smf + 16640;        // 4096 f
    float* s_bo  = smf + 20736;        // 64 f

    const int i = blockIdx.x;
    const int tid = threadIdx.x;
    const int w = tid >> 5, lane = tid & 31;
    const int h = w & 3, qslot = w >> 2;   // qslot 0..3
    const int g = lane >> 2, t = lane & 3;

    // ---- stage K and V as fp16 [h][key][16 d], pitch 24 halfs ----
    {
        const float4* gk4 = (const float4*)(g_k + i * 16384);
        const float4* gv4 = (const float4*)(g_v + i * 16384);
        #pragma unroll
        for (int it = 0; it < 8; ++it) {
            const int idx = it * 512 + tid;
            const int key = idx >> 4, f4 = idx & 15;
            const int hh = f4 >> 2, quad = f4 & 3;
            const int base = (hh * 256 + key) * 12 + quad * 2;
            float4 kv = gk4[idx];
            s_k32[base]     = hpack(kv.x, kv.y);
            s_k32[base + 1] = hpack(kv.z, kv.w);
            float4 vv = gv4[idx];
            s_v32[base]     = hpack(vv.x, vv.y);
            s_v32[base + 1] = hpack(vv.z, vv.w);
        }
    }

    // ldmatrix lane addresses (bytes, shared space)
    u32 sbase;
    asm("{ .reg .u64 tt; cvta.to.shared.u64 tt, %1; cvt.u32.u64 %0, tt; }"
        : "=r"(sbase) : "l"(smf));
    const int rK = (lane & 7) + ((lane >> 4) & 1) * 8;
    const int dK = ((lane >> 3) & 1) * 8;
    const int rV = (lane & 7) + ((lane >> 3) & 1) * 8;
    const int dV = ((lane >> 4) & 1) * 8;
    const u32 kaddr0 = sbase + ((h * 256 + rK) * 24 + dK) * 2;
    const u32 vaddr0 = sbase + 49152 + ((h * 256 + rV) * 24 + dV) * 2;

    __syncthreads();

    float oc[2][2][2][4];
    float inv[2][2][2];
    #pragma unroll 1
    for (int u = 0; u < 2; ++u) {
        const int q0 = qslot * 64 + u * 32;
        float ls[2][2];
        run_unit(i, h, q0, g, t, kaddr0, vaddr0, oc[u], ls);
        #pragma unroll
        for (int mt = 0; mt < 2; ++mt)
            #pragma unroll
            for (int rr = 0; rr < 2; ++rr) {
                float v = ls[mt][rr];
                v += __shfl_xor_sync(0xffffffffu, v, 1);
                v += __shfl_xor_sync(0xffffffffu, v, 2);
                inv[u][mt][rr] = 1.0f / v;
            }
    }

    // normalize + gate (registers only)
    {
        const float2* gp = (const float2*)g_gate;
        #pragma unroll
        for (int u = 0; u < 2; ++u) {
            const int q0 = qslot * 64 + u * 32;
            #pragma unroll
            for (int mt = 0; mt < 2; ++mt) {
                const int qr = i * 256 + q0 + mt * 16 + g;
                #pragma unroll
                for (int nd = 0; nd < 2; ++nd) {
                    float2 g0 = gp[qr * 32 + h * 8 + nd * 4 + t];
                    float2 g1 = gp[(qr + 8) * 32 + h * 8 + nd * 4 + t];
                    oc[u][mt][nd][0] *= inv[u][mt][0] * g0.x;
                    oc[u][mt][nd][1] *= inv[u][mt][0] * g0.y;
                    oc[u][mt][nd][2] *= inv[u][mt][1] * g1.x;
                    oc[u][mt][nd][3] *= inv[u][mt][1] * g1.y;
                }
            }
        }
    }

    __syncthreads();   // all K/V smem reads done; re-use as goT

    // write goT [d][q] stride 260
    #pragma unroll
    for (int u = 0; u < 2; ++u) {
        const int q0 = qslot * 64 + u * 32;
        #pragma unroll
        for (int mt = 0; mt < 2; ++mt) {
            const int qr = q0 + mt * 16 + g;
            #pragma unroll
            for (int nd = 0; nd < 2; ++nd) {
                const int d0 = h * 16 + nd * 8 + 2 * t;
                s_goT[d0 * 260 + qr]           = oc[u][mt][nd][0];
                s_goT[(d0 + 1) * 260 + qr]     = oc[u][mt][nd][1];
                s_goT[d0 * 260 + qr + 8]       = oc[u][mt][nd][2];
                s_goT[(d0 + 1) * 260 + qr + 8] = oc[u][mt][nd][3];
            }
        }
    }
    for (int idx = tid; idx < 4096; idx += 512) s_wo[idx] = Wo[idx];
    if (tid < 64) s_bo[tid] = bo[tid];
    __syncthreads();

    // out = go @ Wo + bo : thread = (col jj, 32-q group pz)
    const int jj = tid & 63;
    const int pz = tid >> 6;    // 0..7
    u64 oa[16];
    #pragma unroll
    for (int m = 0; m < 16; ++m) oa[m] = 0ull;
    #pragma unroll 4
    for (int d = 0; d < 64; ++d) {
        const u64 w2 = dup2(s_wo[d * 64 + jj]);
        const u64* gpt = (const u64*)(s_goT + d * 260 + pz * 32);
        #pragma unroll
        for (int m = 0; m < 16; ++m) fma2(oa[m], gpt[m], w2);
    }
    const float bov = s_bo[jj];
    float* op = out + (i * 256 + pz * 32) * 64 + jj;
    #pragma unroll
    for (int m = 0; m < 16; ++m) {
        float lo, hi;
        unpack2(oa[m], lo, hi);
        op[(2 * m) * 64]     = lo + bov;
        op[(2 * m + 1) * 64] = hi + bov;
    }
}

// ---------------------------------------------------------------------------
extern "C" void kernel_launch(void* const* d_in, const int* in_sizes, int n_in,
                              void* d_out, int out_size)
{
    const float* x    = (const float*)d_in[0];
    const int*   mask = (const int*)d_in[1];
    const float* ln_s = (const float*)d_in[2];
    const float* ln_b = (const float*)d_in[3];
    const float* Wq   = (const float*)d_in[4];
    const float* Wk   = (const float*)d_in[5];
    const float* Wv   = (const float*)d_in[6];
    const float* Wg   = (const float*)d_in[7];
    const float* bg   = (const float*)d_in[8];
    const float* Wb   = (const float*)d_in[9];
    const float* Wo   = (const float*)d_in[10];
    const float* bo   = (const float*)d_in[11];
    float* out = (float*)d_out;
    (void)in_sizes; (void)n_in; (void)out_size;

    const int sm1 = (4 * 4096 + 256 + 64 * 66 + 3 * 64) * (int)sizeof(float);
    const int sm2 = 98304;   // 48 KB K + 48 KB V (epilogue 83.2 KB aliases within)
    cudaFuncSetAttribute(proj_kernel, cudaFuncAttributeMaxDynamicSharedMemorySize, sm1);
    cudaFuncSetAttribute(attn_kernel, cudaFuncAttributeMaxDynamicSharedMemorySize, sm2);

    proj_kernel<<<296, 256, sm1>>>(x, mask, ln_s, ln_b, Wq, Wk, Wv, Wg, bg, Wb);
    attn_kernel<<<256, 512, sm2>>>(Wo, bo, out);
}

// round 17
// speedup vs baseline: 1.3890x; 1.1005x over previous
#include <cuda_runtime.h>
#include <cuda_fp16.h>
#include <math.h>
#include <string.h>

#define NSEQ 256
#define DIM 64
#define NH 4
#define NPOS (NSEQ * NSEQ)
#define NEGINF -1000000000.0f
#define LOG2E 1.4426950408889634f

typedef unsigned long long u64;
typedef unsigned int u32;

// ---- packed fp32x2 helpers (proj + epilogue) ----
__device__ __forceinline__ u64 pack2(float lo, float hi) {
    u64 r; asm("mov.b64 %0, {%1, %2};" : "=l"(r) : "f"(lo), "f"(hi)); return r;
}
__device__ __forceinline__ u64 dup2(float v) { return pack2(v, v); }
__device__ __forceinline__ void unpack2(u64 v, float& lo, float& hi) {
    asm("mov.b64 {%0, %1}, %2;" : "=f"(lo), "=f"(hi) : "l"(v));
}
__device__ __forceinline__ void fma2(u64& d, u64 a, u64 b) {
    asm("fma.rn.f32x2 %0, %1, %2, %0;" : "+l"(d) : "l"(a), "l"(b));
}
__device__ __forceinline__ u64 mul2(u64 a, u64 b) {
    u64 r; asm("mul.rn.f32x2 %0, %1, %2;" : "=l"(r) : "l"(a), "l"(b)); return r;
}

// pack two floats as fp16x2 (low half = a)
__device__ __forceinline__ u32 hpack(float a, float b) {
    __half2 p = __floats2half2_rn(a, b);
    u32 r; memcpy(&r, &p, 4); return r;
}

__device__ __forceinline__ float ex2f(float x) {
    float r; asm("ex2.approx.f32 %0, %1;" : "=f"(r) : "f"(x)); return r;
}

// mma.sync m16n8k16 row.col f32.f16.f16.f32, D = A*B + D
__device__ __forceinline__ void mma16816(float* c, const u32* a, const u32* b) {
    asm volatile(
        "mma.sync.aligned.m16n8k16.row.col.f32.f16.f16.f32 "
        "{%0,%1,%2,%3}, {%4,%5,%6,%7}, {%8,%9}, {%0,%1,%2,%3};"
        : "+f"(c[0]), "+f"(c[1]), "+f"(c[2]), "+f"(c[3])
        : "r"(a[0]), "r"(a[1]), "r"(a[2]), "r"(a[3]), "r"(b[0]), "r"(b[1]));
}

__device__ __forceinline__ void ldsm_x4(u32& r0, u32& r1, u32& r2, u32& r3, u32 addr) {
    asm volatile("ldmatrix.sync.aligned.m8n8.x4.shared.b16 {%0,%1,%2,%3}, [%4];"
                 : "=r"(r0), "=r"(r1), "=r"(r2), "=r"(r3) : "r"(addr));
}
__device__ __forceinline__ void ldsm_x4_t(u32& r0, u32& r1, u32& r2, u32& r3, u32 addr) {
    asm volatile("ldmatrix.sync.aligned.m8n8.x4.trans.shared.b16 {%0,%1,%2,%3}, [%4];"
                 : "=r"(r0), "=r"(r1), "=r"(r2), "=r"(r3) : "r"(addr));
}

// Scratch
__device__ float g_q[NPOS * DIM];
__device__ float g_k[NPOS * DIM];
__device__ float g_v[NPOS * DIM];
__device__ float g_gate[NPOS * DIM];
// bias+mask in MMA C-fragment order:
// float4 index = (h*8 + qtile)*2048 + chunk*128 + part*32 + (g*4 + t)
__device__ float g_bm[NH * NSEQ * NSEQ];

// ---------------------------------------------------------------------------
// Kernel 1 (persistent): LayerNorm + Q/K/V/Gate projections + fused bias/mask.
// ---------------------------------------------------------------------------
__global__ __launch_bounds__(256, 2) void proj_kernel(
    const float* __restrict__ x, const int* __restrict__ mask,
    const float* __restrict__ ln_s, const float* __restrict__ ln_b,
    const float* __restrict__ Wq, const float* __restrict__ Wk,
    const float* __restrict__ Wv, const float* __restrict__ Wg,
    const float* __restrict__ bg, const float* __restrict__ Wb)
{
    extern __shared__ float sm[];
    float* s_wq = sm;                 // 4096
    float* s_wk = s_wq + 4096;
    float* s_wv = s_wk + 4096;
    float* s_wg = s_wv + 4096;
    float* s_wb = s_wg + 4096;        // 256
    float* s_xt = s_wb + 256;         // [d][pos] stride 66
    float* s_bg = s_xt + 64 * 66;
    float* s_ls = s_bg + 64;
    float* s_lb = s_ls + 64;

    const int tid = threadIdx.x;
    for (int idx = tid; idx < 4096; idx += 256) {
        s_wq[idx] = Wq[idx];
        s_wk[idx] = Wk[idx];
        s_wv[idx] = Wv[idx];
        s_wg[idx] = Wg[idx];
    }
    s_wb[tid] = Wb[tid];
    if (tid < 64) { s_bg[tid] = bg[tid]; s_ls[tid] = ln_s[tid]; s_lb[tid] = ln_b[tid]; }
    __syncthreads();

    const int lane = tid & 31;
    const int wrp  = tid >> 5;
    const int jj   = tid & 63;
    const int pz   = tid >> 6;
    const int ph   = tid >> 2;
    const int hh   = tid & 3;

    for (int c = blockIdx.x; c < 1024; c += gridDim.x) {
        const int p0 = c * 64;

        for (int pp = wrp; pp < 64; pp += 8) {
            const float* xr = x + (p0 + pp) * DIM;
            float a = xr[lane];
            float b = xr[lane + 32];
            float sum = a + b;
            float sq = a * a + b * b;
            #pragma unroll
            for (int off = 16; off > 0; off >>= 1) {
                sum += __shfl_xor_sync(0xffffffffu, sum, off);
                sq  += __shfl_xor_sync(0xffffffffu, sq, off);
            }
            float mu  = sum * (1.0f / 64.0f);
            float var = sq * (1.0f / 64.0f) - mu * mu;
            float inv = rsqrtf(var + 1e-5f);
            s_xt[lane * 66 + pp]        = (a - mu) * inv * s_ls[lane]      + s_lb[lane];
            s_xt[(lane + 32) * 66 + pp] = (b - mu) * inv * s_ls[lane + 32] + s_lb[lane + 32];
        }
        __syncthreads();

        // bias + mask -> g_bm in MMA fragment order (pre-scaled by log2 e)
        {
            float acc = 0.0f;
            #pragma unroll 8
            for (int d = 0; d < 64; ++d)
                acc = fmaf(s_xt[d * 66 + ph], s_wb[d * 4 + hh], acc);
            const int flat = p0 + ph;
            const int r  = flat >> 8;    // q
            const int cc = flat & 255;   // k
            const float val = (mask[flat] != 0) ? acc * LOG2E : NEGINF;
            const int qtile = r >> 5;
            const int gg    = r & 7;
            const int part  = ((r >> 4) & 1) * 2 + ((r >> 3) & 1);
            const int chunk = cc >> 4;
            const int nt    = (cc >> 3) & 1;
            const int tt    = (cc >> 1) & 3;
            const int e     = cc & 1;
            const int f4    = (hh * 8 + qtile) * 2048 + chunk * 128 + part * 32 + gg * 4 + tt;
            g_bm[f4 * 4 + nt * 2 + e] = val;
        }

        u64 aq[8], ak[8], av[8], ag[8];
        #pragma unroll
        for (int m = 0; m < 8; ++m) { aq[m] = 0ull; ak[m] = 0ull; av[m] = 0ull; ag[m] = 0ull; }

        #pragma unroll 2
        for (int d = 0; d < 64; ++d) {
            const u64 wq2 = dup2(s_wq[d * 64 + jj]);
            const u64 wk2 = dup2(s_wk[d * 64 + jj]);
            const u64 wv2 = dup2(s_wv[d * 64 + jj]);
            const u64 wg2 = dup2(s_wg[d * 64 + jj]);
            const u64* xp = (const u64*)(s_xt + d * 66 + pz * 16);
            #pragma unroll
            for (int m = 0; m < 8; ++m) {
                const u64 xv = xp[m];
                fma2(aq[m], xv, wq2);
                fma2(ak[m], xv, wk2);
                fma2(av[m], xv, wv2);
                fma2(ag[m], xv, wg2);
            }
        }

        #pragma unroll
        for (int m = 0; m < 8; ++m) {
            const int o = (p0 + pz * 16 + 2 * m) * 64 + jj;
            float v0, v1;
            unpack2(aq[m], v0, v1); g_q[o] = v0; g_q[o + 64] = v1;
            unpack2(ak[m], v0, v1); g_k[o] = v0; g_k[o + 64] = v1;
            unpack2(av[m], v0, v1); g_v[o] = v0; g_v[o + 64] = v1;
            unpack2(ag[m], v0, v1);
            g_gate[o]      = 1.0f / (1.0f + __expf(-(v0 + s_bg[jj])));
            g_gate[o + 64] = 1.0f / (1.0f + __expf(-(v1 + s_bg[jj])));
        }
        __syncthreads();
    }
}

// ---------------------------------------------------------------------------
// Attention unit: warp computes O[32 q][16 d] + row sums for (i, h, q0).
// Software-pipelined: K/V ldmatrix for chunk c+1 issued during chunk c.
// Row sums via ones-MMA (lsacc C-frags; no FADD chain, no shfl reduce).
// ---------------------------------------------------------------------------
__device__ __forceinline__ void run_unit(
    int i, int h, int q0, int g, int t,
    u32 kaddr0, u32 vaddr0,
    float oc[2][2][4], float ls[2][2])
{
    // Q frags (pre-scaled by 1/sqrt(16) * log2(e))
    u32 qa[2][4];
    {
        const float2* qp = (const float2*)g_q;
        const float qs = 0.25f * LOG2E;
        #pragma unroll
        for (int mt = 0; mt < 2; ++mt) {
            const int r0 = i * 256 + q0 + mt * 16 + g;
            float2 f0 = qp[r0 * 32 + h * 8 + t];
            float2 f1 = qp[(r0 + 8) * 32 + h * 8 + t];
            float2 f2 = qp[r0 * 32 + h * 8 + 4 + t];
            float2 f3 = qp[(r0 + 8) * 32 + h * 8 + 4 + t];
            qa[mt][0] = hpack(f0.x * qs, f0.y * qs);
            qa[mt][1] = hpack(f1.x * qs, f1.y * qs);
            qa[mt][2] = hpack(f2.x * qs, f2.y * qs);
            qa[mt][3] = hpack(f3.x * qs, f3.y * qs);
        }
    }
    float lsacc[2][4];
    #pragma unroll
    for (int mt = 0; mt < 2; ++mt) {
        #pragma unroll
        for (int r = 0; r < 4; ++r) { lsacc[mt][r] = 0.f; }
        #pragma unroll
        for (int nd = 0; nd < 2; ++nd)
            #pragma unroll
            for (int r = 0; r < 4; ++r) oc[mt][nd][r] = 0.f;
    }
    const u32 ones2 = 0x3C003C00u;   // (1.0h, 1.0h)
    u32 onesb[2] = {ones2, ones2};

    // bias fragment base: float4 ptr for this (h, qtile), lane g*4+t
    const float4* bp = (const float4*)g_bm + (h * 8 + (q0 >> 5)) * 2048 + (g * 4 + t);

    float scA[2][2][4], scB[2][2][4];

    // prologue: bias chunk 0 -> scA ; K/V chunk 0 -> cur frags
    #pragma unroll
    for (int mt = 0; mt < 2; ++mt)
        #pragma unroll
        for (int rrh = 0; rrh < 2; ++rrh) {
            float4 f = __ldg(bp + (mt * 2 + rrh) * 32);
            scA[mt][0][rrh * 2 + 0] = f.x; scA[mt][0][rrh * 2 + 1] = f.y;
            scA[mt][1][rrh * 2 + 0] = f.z; scA[mt][1][rrh * 2 + 1] = f.w;
        }
    u32 kc[4], vc[4], kn[4], vn[4];
    ldsm_x4(kc[0], kc[1], kc[2], kc[3], kaddr0);
    ldsm_x4_t(vc[0], vc[1], vc[2], vc[3], vaddr0);

    auto body = [&](int c, float sc[2][2][4], float scP[2][2][4],
                    u32 kv0[4], u32 vv0[4], u32 kvn[4], u32 vvn[4]) {
        // QK MMA into sc (already holds bias)
        {
            u32 b0[2] = {kv0[0], kv0[1]}, b1[2] = {kv0[2], kv0[3]};
            #pragma unroll
            for (int mt = 0; mt < 2; ++mt) {
                mma16816(sc[mt][0], qa[mt], b0);
                mma16816(sc[mt][1], qa[mt], b1);
            }
        }
        // prefetch K/V for next chunk (clamped; chunk 15 reloads itself)
        const int cn = (c < 15) ? c + 1 : 15;
        ldsm_x4(kvn[0], kvn[1], kvn[2], kvn[3], kaddr0 + cn * 768);
        ldsm_x4_t(vvn[0], vvn[1], vvn[2], vvn[3], vaddr0 + cn * 768);
        // prefetch bias for next chunk straight into scP (4 coalesced LDG.128)
        #pragma unroll
        for (int mt = 0; mt < 2; ++mt)
            #pragma unroll
            for (int rrh = 0; rrh < 2; ++rrh) {
                float4 f = __ldg(bp + cn * 128 + (mt * 2 + rrh) * 32);
                scP[mt][0][rrh * 2 + 0] = f.x; scP[mt][0][rrh * 2 + 1] = f.y;
                scP[mt][1][rrh * 2 + 0] = f.z; scP[mt][1][rrh * 2 + 1] = f.w;
            }
        // exp2 -> P frags; row sums via ones-MMA
        u32 pa[2][4];
        #pragma unroll
        for (int mt = 0; mt < 2; ++mt) {
            float e00 = ex2f(sc[mt][0][0]);
            float e01 = ex2f(sc[mt][0][1]);
            float e02 = ex2f(sc[mt][0][2]);
            float e03 = ex2f(sc[mt][0][3]);
            float e10 = ex2f(sc[mt][1][0]);
            float e11 = ex2f(sc[mt][1][1]);
            float e12 = ex2f(sc[mt][1][2]);
            float e13 = ex2f(sc[mt][1][3]);
            pa[mt][0] = hpack(e00, e01);
            pa[mt][1] = hpack(e02, e03);
            pa[mt][2] = hpack(e10, e11);
            pa[mt][3] = hpack(e12, e13);
        }
        #pragma unroll
        for (int mt = 0; mt < 2; ++mt)
            mma16816(lsacc[mt], pa[mt], onesb);
        // PV MMAs
        {
            u32 b0[2] = {vv0[0], vv0[1]}, b1[2] = {vv0[2], vv0[3]};
            #pragma unroll
            for (int mt = 0; mt < 2; ++mt) {
                mma16816(oc[mt][0], pa[mt], b0);
                mma16816(oc[mt][1], pa[mt], b1);
            }
        }
    };

    #pragma unroll 1
    for (int cc = 0; cc < 8; ++cc) {
        body(2 * cc,     scA, scB, kc, vc, kn, vn);
        body(2 * cc + 1, scB, scA, kn, vn, kc, vc);
    }

    // all columns of lsacc equal the row sum: c0 = row g, c2 = row g+8
    #pragma unroll
    for (int mt = 0; mt < 2; ++mt) {
        ls[mt][0] = lsacc[mt][0];
        ls[mt][1] = lsacc[mt][2];
    }
}

// ---------------------------------------------------------------------------
// Kernel 2: MMA attention + gate + output projection, fused. Block = row i.
// 512 threads = 16 warps (4/SMSP); warp = (h, q-slot of 64), two 32-q units.
// K/V in smem as [h][256 keys][24 halfs] (48B pitch, ldmatrix-friendly).
// ---------------------------------------------------------------------------
__global__ __launch_bounds__(512, 1) void attn_kernel(
    const float* __restrict__ Wo, const float* __restrict__ bo,
    float* __restrict__ out)
{
    extern __shared__ float smf[];
    u32* s_k32 = (u32*)smf;            // 12288 u32 = 48 KB (pitch 12 u32/key)
    u32* s_v32 = s_k32 + 12288;        // 48 KB
    // epilogue aliases (after sync):
    float* s_goT = smf;                // [64][260] = 66560 B
    float* s_wo  = smf + 16640;        // 4096 f
    float* s_bo  = smf + 20736;        // 64 f

    const int i = blockIdx.x;
    const int tid = threadIdx.x;
    const int w = tid >> 5, lane = tid & 31;
    const int h = w & 3, qslot = w >> 2;   // qslot 0..3
    const int g = lane >> 2, t = lane & 3;

    // ---- stage K and V as fp16 [h][key][16 d], pitch 24 halfs ----
    {
        const float4* gk4 = (const float4*)(g_k + i * 16384);
        const float4* gv4 = (const float4*)(g_v + i * 16384);
        #pragma unroll
        for (int it = 0; it < 8; ++it) {
            const int idx = it * 512 + tid;
            const int key = idx >> 4, f4 = idx & 15;
            const int hh = f4 >> 2, quad = f4 & 3;
            const int base = (hh * 256 + key) * 12 + quad * 2;
            float4 kv = gk4[idx];
            s_k32[base]     = hpack(kv.x, kv.y);
            s_k32[base + 1] = hpack(kv.z, kv.w);
            float4 vv = gv4[idx];
            s_v32[base]     = hpack(vv.x, vv.y);
            s_v32[base + 1] = hpack(vv.z, vv.w);
        }
    }

    // ldmatrix lane addresses (bytes, shared space)
    u32 sbase;
    asm("{ .reg .u64 tt; cvta.to.shared.u64 tt, %1; cvt.u32.u64 %0, tt; }"
        : "=r"(sbase) : "l"(smf));
    const int rK = (lane & 7) + ((lane >> 4) & 1) * 8;
    const int dK = ((lane >> 3) & 1) * 8;
    const int rV = (lane & 7) + ((lane >> 3) & 1) * 8;
    const int dV = ((lane >> 4) & 1) * 8;
    const u32 kaddr0 = sbase + ((h * 256 + rK) * 24 + dK) * 2;
    const u32 vaddr0 = sbase + 49152 + ((h * 256 + rV) * 24 + dV) * 2;

    __syncthreads();

    float oc[2][2][2][4];
    float inv[2][2][2];
    #pragma unroll 1
    for (int u = 0; u < 2; ++u) {
        const int q0 = qslot * 64 + u * 32;
        float ls[2][2];
        run_unit(i, h, q0, g, t, kaddr0, vaddr0, oc[u], ls);
        #pragma unroll
        for (int mt = 0; mt < 2; ++mt)
            #pragma unroll
            for (int rr = 0; rr < 2; ++rr)
                inv[u][mt][rr] = 1.0f / ls[mt][rr];
    }

    // normalize + gate (registers only)
    {
        const float2* gp = (const float2*)g_gate;
        #pragma unroll
        for (int u = 0; u < 2; ++u) {
            const int q0 = qslot * 64 + u * 32;
            #pragma unroll
            for (int mt = 0; mt < 2; ++mt) {
                const int qr = i * 256 + q0 + mt * 16 + g;
                #pragma unroll
                for (int nd = 0; nd < 2; ++nd) {
                    float2 g0 = gp[qr * 32 + h * 8 + nd * 4 + t];
                    float2 g1 = gp[(qr + 8) * 32 + h * 8 + nd * 4 + t];
                    oc[u][mt][nd][0] *= inv[u][mt][0] * g0.x;
                    oc[u][mt][nd][1] *= inv[u][mt][0] * g0.y;
                    oc[u][mt][nd][2] *= inv[u][mt][1] * g1.x;
                    oc[u][mt][nd][3] *= inv[u][mt][1] * g1.y;
                }
            }
        }
    }

    __syncthreads();   // all K/V smem reads done; re-use as goT

    // write goT [d][q] stride 260
    #pragma unroll
    for (int u = 0; u < 2; ++u) {
        const int q0 = qslot * 64 + u * 32;
        #pragma unroll
        for (int mt = 0; mt < 2; ++mt) {
            const int qr = q0 + mt * 16 + g;
            #pragma unroll
            for (int nd = 0; nd < 2; ++nd) {
                const int d0 = h * 16 + nd * 8 + 2 * t;
                s_goT[d0 * 260 + qr]           = oc[u][mt][nd][0];
                s_goT[(d0 + 1) * 260 + qr]     = oc[u][mt][nd][1];
                s_goT[d0 * 260 + qr + 8]       = oc[u][mt][nd][2];
                s_goT[(d0 + 1) * 260 + qr + 8] = oc[u][mt][nd][3];
            }
        }
    }
    for (int idx = tid; idx < 4096; idx += 512) s_wo[idx] = Wo[idx];
    if (tid < 64) s_bo[tid] = bo[tid];
    __syncthreads();

    // out = go @ Wo + bo : thread = (col jj, 32-q group pz)
    const int jj = tid & 63;
    const int pz = tid >> 6;    // 0..7
    u64 oa[16];
    #pragma unroll
    for (int m = 0; m < 16; ++m) oa[m] = 0ull;
    #pragma unroll 4
    for (int d = 0; d < 64; ++d) {
        const u64 w2 = dup2(s_wo[d * 64 + jj]);
        const u64* gpt = (const u64*)(s_goT + d * 260 + pz * 32);
        #pragma unroll
        for (int m = 0; m < 16; ++m) fma2(oa[m], gpt[m], w2);
    }
    const float bov = s_bo[jj];
    float* op = out + (i * 256 + pz * 32) * 64 + jj;
    #pragma unroll
    for (int m = 0; m < 16; ++m) {
        float lo, hi;
        unpack2(oa[m], lo, hi);
        op[(2 * m) * 64]     = lo + bov;
        op[(2 * m + 1) * 64] = hi + bov;
    }
}

// ---------------------------------------------------------------------------
extern "C" void kernel_launch(void* const* d_in, const int* in_sizes, int n_in,
                              void* d_out, int out_size)
{
    const float* x    = (const float*)d_in[0];
    const int*   mask = (const int*)d_in[1];
    const float* ln_s = (const float*)d_in[2];
    const float* ln_b = (const float*)d_in[3];
    const float* Wq   = (const float*)d_in[4];
    const float* Wk   = (const float*)d_in[5];
    const float* Wv   = (const float*)d_in[6];
    const float* Wg   = (const float*)d_in[7];
    const float* bg   = (const float*)d_in[8];
    const float* Wb   = (const float*)d_in[9];
    const float* Wo   = (const float*)d_in[10];
    const float* bo   = (const float*)d_in[11];
    float* out = (float*)d_out;
    (void)in_sizes; (void)n_in; (void)out_size;

    const int sm1 = (4 * 4096 + 256 + 64 * 66 + 3 * 64) * (int)sizeof(float);
    const int sm2 = 98304;   // 48 KB K + 48 KB V (epilogue 83.2 KB aliases within)
    cudaFuncSetAttribute(proj_kernel, cudaFuncAttributeMaxDynamicSharedMemorySize, sm1);
    cudaFuncSetAttribute(attn_kernel, cudaFuncAttributeMaxDynamicSharedMemorySize, sm2);

    proj_kernel<<<296, 256, sm1>>>(x, mask, ln_s, ln_b, Wq, Wk, Wv, Wg, bg, Wb);
    attn_kernel<<<256, 512, sm2>>>(Wo, bo, out);
}